// round 2
// baseline (speedup 1.0000x reference)
#include <cuda_runtime.h>
#include <cuda_bf16.h>

// ---------------- problem constants (from reference) ----------------
#define NN 50000
#define EE 400000
#define DD 128
#define HH 60
#define H3 180
#define CC 40
#define BN_EPS 1e-5f

// ---------------- static scratch (__device__ globals; no allocs) ----
__device__ float g_T1[NN * H3];
__device__ float g_T2[NN * H3];
__device__ float g_Ha[NN * H3];
__device__ float g_Hb[NN * H3];
__device__ int   g_cnt[NN];
__device__ int   g_ptr[NN + 1];
__device__ int   g_cursor[NN];
__device__ int   g_srcIdx[EE];
__device__ float g_enorm[EE];
__device__ float g_dis[NN];

// ---------------- CSR build ----------------
__global__ void hist_kernel(const int* __restrict__ col, int* __restrict__ cnt, int E) {
    int e = blockIdx.x * blockDim.x + threadIdx.x;
    if (e < E) atomicAdd(&cnt[col[e]], 1);
}

__global__ void dis_kernel(const int* __restrict__ cnt, float* __restrict__ dis, int n) {
    int i = blockIdx.x * blockDim.x + threadIdx.x;
    if (i < n) dis[i] = rsqrtf((float)(cnt[i] + 1));  // +1 self loop; deg >= 1 always
}

// single-block chunked exclusive scan over n counts -> ptr[0..n], cursor copy
__global__ void scan_kernel(const int* __restrict__ cnt, int* __restrict__ ptr,
                            int* __restrict__ cursor, int n) {
    __shared__ int sdata[1024];
    __shared__ int s_carry;
    int tid = threadIdx.x;
    if (tid == 0) s_carry = 0;
    __syncthreads();
    for (int base = 0; base < n; base += 1024) {
        int i = base + tid;
        int v = (i < n) ? cnt[i] : 0;
        sdata[tid] = v;
        __syncthreads();
        #pragma unroll
        for (int off = 1; off < 1024; off <<= 1) {
            int t = (tid >= off) ? sdata[tid - off] : 0;
            __syncthreads();
            sdata[tid] += t;
            __syncthreads();
        }
        int excl = sdata[tid] - v + s_carry;
        if (i < n) { ptr[i] = excl; cursor[i] = excl; }
        __syncthreads();
        if (tid == 1023) s_carry += sdata[1023];
        __syncthreads();
    }
    if (tid == 0) ptr[n] = s_carry;
}

__global__ void scatter_kernel(const int* __restrict__ row, const int* __restrict__ col,
                               const float* __restrict__ dis, int* __restrict__ cursor,
                               int* __restrict__ srcIdx, float* __restrict__ enorm, int E) {
    int e = blockIdx.x * blockDim.x + threadIdx.x;
    if (e < E) {
        int r = row[e], c = col[e];
        int pos = atomicAdd(&cursor[c], 1);
        srcIdx[pos] = r;
        enorm[pos]  = dis[r] * dis[c];
    }
}

// ---------------- SpMM: out[i] = dis[i]^2 * in[i] + sum_{e: col=i} enorm[e] * in[src[e]] ----
template <int F>
__global__ void spmm_kernel(const float* __restrict__ in, float* __restrict__ out,
                            const int* __restrict__ ptr, const int* __restrict__ srcIdx,
                            const float* __restrict__ enorm, const float* __restrict__ dis) {
    int i = blockIdx.x;
    int f = threadIdx.x;
    if (f >= F) return;
    float d = dis[i];
    float acc = d * d * in[i * F + f];
    int s = ptr[i], e = ptr[i + 1];
    for (int k = s; k < e; k++) {
        acc += enorm[k] * in[srcIdx[k] * F + f];
    }
    out[i * F + f] = acc;
}

// ---------------- GEMM (+ optional fused BatchNorm epilogue) ----------------
// Computes out[:, colOff + 0..Cc) = A_p @ W_p^T + b_p (then BN), p = blockIdx.y.
// 64-row x <=64-col tile, 256 threads, 4x4 register blocking, K chunked by 32.
template <bool BN>
__global__ void gemm_kernel(const float* __restrict__ A0, const float* __restrict__ A1,
                            const float* __restrict__ A2,
                            const float* __restrict__ W, const float* __restrict__ bias,
                            const float* __restrict__ bng, const float* __restrict__ bnb,
                            const float* __restrict__ bnm, const float* __restrict__ bnv,
                            float* __restrict__ out, int N, int K, int Cc, int ldOut) {
    const int p = blockIdx.y;
    const float* A  = (p == 0) ? A0 : ((p == 1) ? A1 : A2);
    const float* Wp = W + p * Cc * K;
    const float* bp = bias + p * Cc;
    const int colOff = p * Cc;

    __shared__ float sA[64][33];
    __shared__ float sW[32][65];

    const int tid = threadIdx.x;
    const int tx = tid & 15;       // col group
    const int ty = tid >> 4;       // row group
    const int row0 = blockIdx.x * 64;

    float acc[4][4];
    #pragma unroll
    for (int i = 0; i < 4; i++)
        #pragma unroll
        for (int j = 0; j < 4; j++) acc[i][j] = 0.0f;

    for (int kb = 0; kb < K; kb += 32) {
        // load A tile [64 x 32]
        #pragma unroll
        for (int t = 0; t < 8; t++) {
            int idx = tid + t * 256;
            int r = idx >> 5, k = idx & 31;
            int gr = row0 + r, gk = kb + k;
            sA[r][k] = (gr < N && gk < K) ? A[(size_t)gr * K + gk] : 0.0f;
        }
        // load W tile transposed [32 x Cc]
        #pragma unroll
        for (int t = 0; t < 8; t++) {
            int idx = tid + t * 256;
            int c = idx >> 5, k = idx & 31;
            int gk = kb + k;
            sW[k][c] = (c < Cc && gk < K) ? Wp[(size_t)c * K + gk] : 0.0f;
        }
        __syncthreads();

        #pragma unroll
        for (int k = 0; k < 32; k++) {
            float a[4], w[4];
            #pragma unroll
            for (int j = 0; j < 4; j++) a[j] = sA[ty * 4 + j][k];
            #pragma unroll
            for (int j = 0; j < 4; j++) w[j] = sW[k][tx * 4 + j];
            #pragma unroll
            for (int i = 0; i < 4; i++)
                #pragma unroll
                for (int j = 0; j < 4; j++) acc[i][j] += a[i] * w[j];
        }
        __syncthreads();
    }

    // epilogue: bias + (optional) BN fold
    #pragma unroll
    for (int j = 0; j < 4; j++) {
        int c = tx * 4 + j;
        if (c >= Cc) continue;
        float add = bp[c];
        float scale = 1.0f, shift = 0.0f;
        if (BN) {
            int cg = colOff + c;
            scale = bng[cg] * rsqrtf(bnv[cg] + BN_EPS);
            shift = bnb[cg] - bnm[cg] * scale;
        }
        #pragma unroll
        for (int i = 0; i < 4; i++) {
            int r = row0 + ty * 4 + i;
            if (r < N) {
                float z = acc[i][j] + add;
                float v = BN ? (z * scale + shift) : z;
                out[(size_t)r * ldOut + colOff + c] = v;
            }
        }
    }
}

// ---------------- host launch ----------------
extern "C" void kernel_launch(void* const* d_in, const int* in_sizes, int n_in,
                              void* d_out, int out_size) {
    const float* x       = (const float*)d_in[0];
    const int*   ei      = (const int*)d_in[1];
    const float* conv1_W = (const float*)d_in[2];
    const float* conv1_b = (const float*)d_in[3];
    const float* conv2_W = (const float*)d_in[4];
    const float* conv2_b = (const float*)d_in[5];
    const float* conv3_W = (const float*)d_in[6];
    const float* conv3_b = (const float*)d_in[7];
    const float* bn1_g = (const float*)d_in[8];
    const float* bn1_b = (const float*)d_in[9];
    const float* bn1_m = (const float*)d_in[10];
    const float* bn1_v = (const float*)d_in[11];
    const float* bn2_g = (const float*)d_in[12];
    const float* bn2_b = (const float*)d_in[13];
    const float* bn2_m = (const float*)d_in[14];
    const float* bn2_v = (const float*)d_in[15];
    const float* bn3_g = (const float*)d_in[16];
    const float* bn3_b = (const float*)d_in[17];
    const float* bn3_m = (const float*)d_in[18];
    const float* bn3_v = (const float*)d_in[19];
    const float* lin_W = (const float*)d_in[20];
    const float* lin_b = (const float*)d_in[21];
    float* out = (float*)d_out;

    const int N = in_sizes[0] / DD;
    const int E = in_sizes[1] / 2;

    float *T1, *T2, *Ha, *Hb, *enorm, *dis;
    int *cnt, *ptr, *cursor, *srcIdx;
    cudaGetSymbolAddress((void**)&T1, g_T1);
    cudaGetSymbolAddress((void**)&T2, g_T2);
    cudaGetSymbolAddress((void**)&Ha, g_Ha);
    cudaGetSymbolAddress((void**)&Hb, g_Hb);
    cudaGetSymbolAddress((void**)&cnt, g_cnt);
    cudaGetSymbolAddress((void**)&ptr, g_ptr);
    cudaGetSymbolAddress((void**)&cursor, g_cursor);
    cudaGetSymbolAddress((void**)&srcIdx, g_srcIdx);
    cudaGetSymbolAddress((void**)&enorm, g_enorm);
    cudaGetSymbolAddress((void**)&dis, g_dis);

    const int* e_row = ei;
    const int* e_col = ei + E;

    // ---- CSR build ----
    cudaMemsetAsync(cnt, 0, N * sizeof(int));
    hist_kernel<<<(E + 255) / 256, 256>>>(e_col, cnt, E);
    dis_kernel<<<(N + 255) / 256, 256>>>(cnt, dis, N);
    scan_kernel<<<1, 1024>>>(cnt, ptr, cursor, N);
    scatter_kernel<<<(E + 255) / 256, 256>>>(e_row, e_col, dis, cursor, srcIdx, enorm, E);

    dim3 gemmGrid3((N + 63) / 64, 3);
    dim3 gemmGrid1((N + 63) / 64, 1);

    // ---- layer 1 (K = 128) ----
    spmm_kernel<DD><<<N, 128>>>(x, T1, ptr, srcIdx, enorm, dis);
    spmm_kernel<DD><<<N, 128>>>(T1, T2, ptr, srcIdx, enorm, dis);
    gemm_kernel<true><<<gemmGrid3, 256>>>(x, T1, T2, conv1_W, conv1_b,
                                          bn1_g, bn1_b, bn1_m, bn1_v,
                                          Ha, N, DD, HH, H3);

    // ---- layer 2 (K = 180) ----
    spmm_kernel<H3><<<N, 192>>>(Ha, T1, ptr, srcIdx, enorm, dis);
    spmm_kernel<H3><<<N, 192>>>(T1, T2, ptr, srcIdx, enorm, dis);
    gemm_kernel<true><<<gemmGrid3, 256>>>(Ha, T1, T2, conv2_W, conv2_b,
                                          bn2_g, bn2_b, bn2_m, bn2_v,
                                          Hb, N, H3, HH, H3);

    // ---- layer 3 (K = 180) ----
    spmm_kernel<H3><<<N, 192>>>(Hb, T1, ptr, srcIdx, enorm, dis);
    spmm_kernel<H3><<<N, 192>>>(T1, T2, ptr, srcIdx, enorm, dis);
    gemm_kernel<true><<<gemmGrid3, 256>>>(Hb, T1, T2, conv3_W, conv3_b,
                                          bn3_g, bn3_b, bn3_m, bn3_v,
                                          Ha, N, H3, HH, H3);

    // ---- final linear (no BN) ----
    gemm_kernel<false><<<gemmGrid1, 256>>>(Ha, Ha, Ha, lin_W, lin_b,
                                           nullptr, nullptr, nullptr, nullptr,
                                           out, N, H3, CC, CC);
}

// round 3
// speedup vs baseline: 1.1398x; 1.1398x over previous
#include <cuda_runtime.h>
#include <cuda_bf16.h>

// ---------------- problem constants (from reference) ----------------
#define NN 50000
#define EE 400000
#define DD 128
#define HH 60
#define H3 180
#define CC 40
#define BN_EPS 1e-5f

// ---------------- static scratch (__device__ globals; no allocs) ----
__device__ float g_T1[NN * H3];
__device__ float g_T2[NN * H3];
__device__ float g_Ha[NN * H3];
__device__ float g_Hb[NN * H3];
__device__ int   g_cnt[NN];
__device__ int   g_ptr[NN + 1];
__device__ int   g_cursor[NN];
__device__ int   g_srcIdx[EE];
__device__ float g_enorm[EE];
__device__ float g_dis[NN];

// ---------------- CSR build ----------------
__global__ void hist_kernel(const int* __restrict__ col, int* __restrict__ cnt, int E) {
    int e = blockIdx.x * blockDim.x + threadIdx.x;
    if (e < E) atomicAdd(&cnt[col[e]], 1);
}

__global__ void dis_kernel(const int* __restrict__ cnt, float* __restrict__ dis, int n) {
    int i = blockIdx.x * blockDim.x + threadIdx.x;
    if (i < n) dis[i] = rsqrtf((float)(cnt[i] + 1));  // +1 self loop; deg >= 1 always
}

// single-block chunked exclusive scan over n counts -> ptr[0..n], cursor copy
__global__ void scan_kernel(const int* __restrict__ cnt, int* __restrict__ ptr,
                            int* __restrict__ cursor, int n) {
    __shared__ int sdata[1024];
    __shared__ int s_carry;
    int tid = threadIdx.x;
    if (tid == 0) s_carry = 0;
    __syncthreads();
    for (int base = 0; base < n; base += 1024) {
        int i = base + tid;
        int v = (i < n) ? cnt[i] : 0;
        sdata[tid] = v;
        __syncthreads();
        #pragma unroll
        for (int off = 1; off < 1024; off <<= 1) {
            int t = (tid >= off) ? sdata[tid - off] : 0;
            __syncthreads();
            sdata[tid] += t;
            __syncthreads();
        }
        int excl = sdata[tid] - v + s_carry;
        if (i < n) { ptr[i] = excl; cursor[i] = excl; }
        __syncthreads();
        if (tid == 1023) s_carry += sdata[1023];
        __syncthreads();
    }
    if (tid == 0) ptr[n] = s_carry;
}

__global__ void scatter_kernel(const int* __restrict__ row, const int* __restrict__ col,
                               const float* __restrict__ dis, int* __restrict__ cursor,
                               int* __restrict__ srcIdx, float* __restrict__ enorm, int E) {
    int e = blockIdx.x * blockDim.x + threadIdx.x;
    if (e < E) {
        int r = row[e], c = col[e];
        int pos = atomicAdd(&cursor[c], 1);
        srcIdx[pos] = r;
        enorm[pos]  = dis[r] * dis[c];
    }
}

// ---------------- SpMM: out[i] = dis[i]^2 * in[i] + sum_{e: col=i} enorm[e] * in[src[e]] ----
template <int F>
__global__ void spmm_kernel(const float* __restrict__ in, float* __restrict__ out,
                            const int* __restrict__ ptr, const int* __restrict__ srcIdx,
                            const float* __restrict__ enorm, const float* __restrict__ dis) {
    int i = blockIdx.x;
    int f = threadIdx.x;
    if (f >= F) return;
    float d = dis[i];
    float acc = d * d * in[i * F + f];
    int s = ptr[i], e = ptr[i + 1];
    for (int k = s; k < e; k++) {
        acc += enorm[k] * in[srcIdx[k] * F + f];
    }
    out[i * F + f] = acc;
}

// ---------------- tensor-core GEMM (3xTF32 + fused BN epilogue) ----------------
// out[:, colOff + 0..Cc) = A_p @ W_p^T + b_p (then BN); p = blockIdx.y selects A/W slice.
// Block tile 64 rows x 64 cols (Cc<=64 masked), 8 warps (4 along M x 2 along N),
// warp tile 16x32 = 4 mma n-tiles, K chunked by 32 (zero-padded).
// 3xTF32: a ~= a_hi + a_lo; D += a_hi*b_hi + a_hi*b_lo + a_lo*b_hi  (~fp32 accuracy).

__device__ __forceinline__ unsigned f2tf(float f) {
    unsigned r;
    asm("cvt.rna.tf32.f32 %0, %1;" : "=r"(r) : "f"(f));
    return r;
}

__device__ __forceinline__ void mma_tf32(float& d0, float& d1, float& d2, float& d3,
                                         unsigned a0, unsigned a1, unsigned a2, unsigned a3,
                                         unsigned b0, unsigned b1) {
    asm volatile("mma.sync.aligned.m16n8k8.row.col.f32.tf32.tf32.f32 "
                 "{%0,%1,%2,%3}, {%4,%5,%6,%7}, {%8,%9}, {%0,%1,%2,%3};"
                 : "+f"(d0), "+f"(d1), "+f"(d2), "+f"(d3)
                 : "r"(a0), "r"(a1), "r"(a2), "r"(a3), "r"(b0), "r"(b1));
}

template <bool BN>
__global__ void __launch_bounds__(256)
gemm_tc_kernel(const float* __restrict__ A0, const float* __restrict__ A1,
               const float* __restrict__ A2,
               const float* __restrict__ W, const float* __restrict__ bias,
               const float* __restrict__ bng, const float* __restrict__ bnb,
               const float* __restrict__ bnm, const float* __restrict__ bnv,
               float* __restrict__ out, int N, int K, int Cc, int ldOut) {
    const int p = blockIdx.y;
    const float* A  = (p == 0) ? A0 : ((p == 1) ? A1 : A2);
    const float* Wp = W + p * Cc * K;
    const float* bp = bias + p * Cc;
    const int colOff = p * Cc;

    // pad 36: bank = (36*r + c) % 32 = (4r + c) % 32 -> conflict-free for frag loads
    __shared__ unsigned sAh[64][36];
    __shared__ unsigned sAl[64][36];
    __shared__ unsigned sWh[64][36];
    __shared__ unsigned sWl[64][36];

    const int tid  = threadIdx.x;
    const int lane = tid & 31;
    const int wid  = tid >> 5;
    const int warpM = wid & 3;   // 0..3 -> 16-row slices
    const int warpN = wid >> 2;  // 0..1 -> 32-col slices
    const int row0 = blockIdx.x * 64;

    const int g = lane >> 2;     // groupID 0..7
    const int t = lane & 3;      // thread-in-group 0..3

    float acc[4][4];             // 4 n-tiles x 4 regs
    #pragma unroll
    for (int nt = 0; nt < 4; nt++)
        #pragma unroll
        for (int j = 0; j < 4; j++) acc[nt][j] = 0.0f;

    const int nChunks = (K + 31) / 32;
    for (int kb = 0; kb < nChunks * 32; kb += 32) {
        // --- load A tile [64 x 32] as hi/lo tf32 ---
        #pragma unroll
        for (int it = 0; it < 8; it++) {
            int idx = tid + it * 256;
            int r = idx >> 5, k = idx & 31;
            int gr = row0 + r, gk = kb + k;
            float v = (gr < N && gk < K) ? A[(size_t)gr * K + gk] : 0.0f;
            unsigned hi = f2tf(v);
            sAh[r][k] = hi;
            sAl[r][k] = f2tf(v - __uint_as_float(hi));
        }
        // --- load W tile [64 x 32] (rows = output cols) as hi/lo tf32 ---
        #pragma unroll
        for (int it = 0; it < 8; it++) {
            int idx = tid + it * 256;
            int c = idx >> 5, k = idx & 31;
            int gk = kb + k;
            float v = (c < Cc && gk < K) ? Wp[(size_t)c * K + gk] : 0.0f;
            unsigned hi = f2tf(v);
            sWh[c][k] = hi;
            sWl[c][k] = f2tf(v - __uint_as_float(hi));
        }
        __syncthreads();

        #pragma unroll
        for (int ks = 0; ks < 4; ks++) {
            const int k0 = ks * 8;
            const int ar = warpM * 16 + g;
            // A fragment (m16k8): a0(r,c) a1(r+8,c) a2(r,c+4) a3(r+8,c+4)
            unsigned ah0 = sAh[ar][k0 + t];
            unsigned ah1 = sAh[ar + 8][k0 + t];
            unsigned ah2 = sAh[ar][k0 + t + 4];
            unsigned ah3 = sAh[ar + 8][k0 + t + 4];
            unsigned al0 = sAl[ar][k0 + t];
            unsigned al1 = sAl[ar + 8][k0 + t];
            unsigned al2 = sAl[ar][k0 + t + 4];
            unsigned al3 = sAl[ar + 8][k0 + t + 4];
            #pragma unroll
            for (int nt = 0; nt < 4; nt++) {
                const int bn_ = warpN * 32 + nt * 8 + g;
                // B fragment (k8n8 col): b0(k=t, n) b1(k=t+4, n)
                unsigned bh0 = sWh[bn_][k0 + t];
                unsigned bh1 = sWh[bn_][k0 + t + 4];
                unsigned bl0 = sWl[bn_][k0 + t];
                unsigned bl1 = sWl[bn_][k0 + t + 4];
                mma_tf32(acc[nt][0], acc[nt][1], acc[nt][2], acc[nt][3],
                         ah0, ah1, ah2, ah3, bh0, bh1);
                mma_tf32(acc[nt][0], acc[nt][1], acc[nt][2], acc[nt][3],
                         ah0, ah1, ah2, ah3, bl0, bl1);
                mma_tf32(acc[nt][0], acc[nt][1], acc[nt][2], acc[nt][3],
                         al0, al1, al2, al3, bh0, bh1);
            }
        }
        __syncthreads();
    }

    // --- epilogue: bias + optional BN fold ---
    const int rlo = row0 + warpM * 16 + g;
    #pragma unroll
    for (int nt = 0; nt < 4; nt++) {
        const int cb = warpN * 32 + nt * 8 + 2 * t;
        #pragma unroll
        for (int jj = 0; jj < 2; jj++) {
            int c = cb + jj;
            if (c >= Cc) continue;
            float add = bp[c];
            float scale = 1.0f, shift = 0.0f;
            if (BN) {
                int cg = colOff + c;
                scale = bng[cg] * rsqrtf(bnv[cg] + BN_EPS);
                shift = bnb[cg] - bnm[cg] * scale;
            }
            float v0 = acc[nt][jj] + add;       // row rlo
            float v1 = acc[nt][2 + jj] + add;   // row rlo+8
            if (BN) { v0 = v0 * scale + shift; v1 = v1 * scale + shift; }
            if (rlo < N)     out[(size_t)rlo * ldOut + colOff + c] = v0;
            if (rlo + 8 < N) out[(size_t)(rlo + 8) * ldOut + colOff + c] = v1;
        }
    }
}

// ---------------- host launch ----------------
extern "C" void kernel_launch(void* const* d_in, const int* in_sizes, int n_in,
                              void* d_out, int out_size) {
    const float* x       = (const float*)d_in[0];
    const int*   ei      = (const int*)d_in[1];
    const float* conv1_W = (const float*)d_in[2];
    const float* conv1_b = (const float*)d_in[3];
    const float* conv2_W = (const float*)d_in[4];
    const float* conv2_b = (const float*)d_in[5];
    const float* conv3_W = (const float*)d_in[6];
    const float* conv3_b = (const float*)d_in[7];
    const float* bn1_g = (const float*)d_in[8];
    const float* bn1_b = (const float*)d_in[9];
    const float* bn1_m = (const float*)d_in[10];
    const float* bn1_v = (const float*)d_in[11];
    const float* bn2_g = (const float*)d_in[12];
    const float* bn2_b = (const float*)d_in[13];
    const float* bn2_m = (const float*)d_in[14];
    const float* bn2_v = (const float*)d_in[15];
    const float* bn3_g = (const float*)d_in[16];
    const float* bn3_b = (const float*)d_in[17];
    const float* bn3_m = (const float*)d_in[18];
    const float* bn3_v = (const float*)d_in[19];
    const float* lin_W = (const float*)d_in[20];
    const float* lin_b = (const float*)d_in[21];
    float* out = (float*)d_out;

    const int N = in_sizes[0] / DD;
    const int E = in_sizes[1] / 2;

    float *T1, *T2, *Ha, *Hb, *enorm, *dis;
    int *cnt, *ptr, *cursor, *srcIdx;
    cudaGetSymbolAddress((void**)&T1, g_T1);
    cudaGetSymbolAddress((void**)&T2, g_T2);
    cudaGetSymbolAddress((void**)&Ha, g_Ha);
    cudaGetSymbolAddress((void**)&Hb, g_Hb);
    cudaGetSymbolAddress((void**)&cnt, g_cnt);
    cudaGetSymbolAddress((void**)&ptr, g_ptr);
    cudaGetSymbolAddress((void**)&cursor, g_cursor);
    cudaGetSymbolAddress((void**)&srcIdx, g_srcIdx);
    cudaGetSymbolAddress((void**)&enorm, g_enorm);
    cudaGetSymbolAddress((void**)&dis, g_dis);

    const int* e_row = ei;
    const int* e_col = ei + E;

    // ---- CSR build ----
    cudaMemsetAsync(cnt, 0, N * sizeof(int));
    hist_kernel<<<(E + 255) / 256, 256>>>(e_col, cnt, E);
    dis_kernel<<<(N + 255) / 256, 256>>>(cnt, dis, N);
    scan_kernel<<<1, 1024>>>(cnt, ptr, cursor, N);
    scatter_kernel<<<(E + 255) / 256, 256>>>(e_row, e_col, dis, cursor, srcIdx, enorm, E);

    dim3 gemmGrid3((N + 63) / 64, 3);
    dim3 gemmGrid1((N + 63) / 64, 1);

    // ---- layer 1 (K = 128) ----
    spmm_kernel<DD><<<N, 128>>>(x, T1, ptr, srcIdx, enorm, dis);
    spmm_kernel<DD><<<N, 128>>>(T1, T2, ptr, srcIdx, enorm, dis);
    gemm_tc_kernel<true><<<gemmGrid3, 256>>>(x, T1, T2, conv1_W, conv1_b,
                                             bn1_g, bn1_b, bn1_m, bn1_v,
                                             Ha, N, DD, HH, H3);

    // ---- layer 2 (K = 180) ----
    spmm_kernel<H3><<<N, 192>>>(Ha, T1, ptr, srcIdx, enorm, dis);
    spmm_kernel<H3><<<N, 192>>>(T1, T2, ptr, srcIdx, enorm, dis);
    gemm_tc_kernel<true><<<gemmGrid3, 256>>>(Ha, T1, T2, conv2_W, conv2_b,
                                             bn2_g, bn2_b, bn2_m, bn2_v,
                                             Hb, N, H3, HH, H3);

    // ---- layer 3 (K = 180) ----
    spmm_kernel<H3><<<N, 192>>>(Hb, T1, ptr, srcIdx, enorm, dis);
    spmm_kernel<H3><<<N, 192>>>(T1, T2, ptr, srcIdx, enorm, dis);
    gemm_tc_kernel<true><<<gemmGrid3, 256>>>(Hb, T1, T2, conv3_W, conv3_b,
                                             bn3_g, bn3_b, bn3_m, bn3_v,
                                             Ha, N, H3, HH, H3);

    // ---- final linear (no BN) ----
    gemm_tc_kernel<false><<<gemmGrid1, 256>>>(Ha, Ha, Ha, lin_W, lin_b,
                                              nullptr, nullptr, nullptr, nullptr,
                                              out, N, H3, CC, CC);
}

// round 5
// speedup vs baseline: 1.9743x; 1.7322x over previous
#include <cuda_runtime.h>
#include <cuda_bf16.h>

// ---------------- problem constants ----------------
#define NN 50000
#define EE 400000
#define DD 128
#define HH 60
#define H3 180
#define CC 40
#define BN_EPS 1e-5f

// ---------------- static scratch ----------------
__device__ float g_T1[NN * H3];
__device__ float g_T2[NN * H3];
__device__ float g_Ha[NN * H3];
__device__ float g_Hb[NN * H3];
__device__ int   g_cnt[NN];
__device__ int   g_ptr[NN + 1];
__device__ int   g_cursor[NN];
__device__ int   g_srcIdx[EE];
__device__ float g_enorm[EE];
__device__ float g_dis[NN];

// ---------------- CSR build ----------------
__global__ void hist_kernel(const int* __restrict__ col, int* __restrict__ cnt, int E) {
    int e = blockIdx.x * blockDim.x + threadIdx.x;
    if (e < E) atomicAdd(&cnt[col[e]], 1);
}

__global__ void dis_kernel(const int* __restrict__ cnt, float* __restrict__ dis, int n) {
    int i = blockIdx.x * blockDim.x + threadIdx.x;
    if (i < n) dis[i] = rsqrtf((float)(cnt[i] + 1));  // +1 self loop
}

// single-block shuffle-based exclusive scan
__global__ void scan_kernel(const int* __restrict__ cnt, int* __restrict__ ptr,
                            int* __restrict__ cursor, int n) {
    __shared__ int wincl[32];
    const int tid = threadIdx.x, lane = tid & 31, wid = tid >> 5;
    int carry = 0;
    for (int base = 0; base < n; base += 1024) {
        int i = base + tid;
        int v = (i < n) ? cnt[i] : 0;
        int x = v;
        #pragma unroll
        for (int off = 1; off < 32; off <<= 1) {
            int t = __shfl_up_sync(0xffffffffu, x, off);
            if (lane >= off) x += t;
        }
        if (lane == 31) wincl[wid] = x;
        __syncthreads();
        if (wid == 0) {
            int w = wincl[lane];
            #pragma unroll
            for (int off = 1; off < 32; off <<= 1) {
                int t = __shfl_up_sync(0xffffffffu, w, off);
                if (lane >= off) w += t;
            }
            wincl[lane] = w;
        }
        __syncthreads();
        int woff = wid ? wincl[wid - 1] : 0;
        int excl = carry + woff + x - v;
        if (i < n) { ptr[i] = excl; cursor[i] = excl; }
        carry += wincl[31];
        __syncthreads();
    }
    if (tid == 0) ptr[n] = carry;
}

__global__ void scatter_kernel(const int* __restrict__ row, const int* __restrict__ col,
                               const float* __restrict__ dis, int* __restrict__ cursor,
                               int* __restrict__ srcIdx, float* __restrict__ enorm, int E) {
    int e = blockIdx.x * blockDim.x + threadIdx.x;
    if (e < E) {
        int r = row[e], c = col[e];
        int pos = atomicAdd(&cursor[c], 1);
        srcIdx[pos] = r;
        enorm[pos]  = dis[r] * dis[c];
    }
}

// ---------------- SpMM v2: warp-per-node, float4 gather ----------------
// out[i] = dis[i]^2 * in[i] + sum_{e: col=i} enorm[e] * in[src[e]]
template <int F4>   // float4 per row: 32 (F=128) or 45 (F=180)
__global__ void __launch_bounds__(256)
spmm_v2(const float4* __restrict__ in, float4* __restrict__ out,
        const int* __restrict__ ptr, const int* __restrict__ srcIdx,
        const float* __restrict__ enorm, const float* __restrict__ dis, int N) {
    const int lane = threadIdx.x & 31;
    const int node = blockIdx.x * 8 + (threadIdx.x >> 5);
    if (node >= N) return;
    const bool two = (F4 > 32) && (lane < F4 - 32);

    float d = dis[node];
    float dd = d * d;
    float4 a0 = in[node * F4 + lane];
    a0.x *= dd; a0.y *= dd; a0.z *= dd; a0.w *= dd;
    float4 a1 = make_float4(0.f, 0.f, 0.f, 0.f);
    if (two) {
        float4 v = in[node * F4 + 32 + lane];
        a1.x = dd * v.x; a1.y = dd * v.y; a1.z = dd * v.z; a1.w = dd * v.w;
    }

    int s = ptr[node], e = ptr[node + 1];
    int k = s;
    for (; k + 1 < e; k += 2) {
        int s0 = srcIdx[k], s1 = srcIdx[k + 1];
        float w0 = enorm[k], w1 = enorm[k + 1];
        float4 v0 = in[s0 * F4 + lane];
        float4 v1 = in[s1 * F4 + lane];
        a0.x += w0 * v0.x; a0.y += w0 * v0.y; a0.z += w0 * v0.z; a0.w += w0 * v0.w;
        a0.x += w1 * v1.x; a0.y += w1 * v1.y; a0.z += w1 * v1.z; a0.w += w1 * v1.w;
        if (two) {
            float4 u0 = in[s0 * F4 + 32 + lane];
            float4 u1 = in[s1 * F4 + 32 + lane];
            a1.x += w0 * u0.x; a1.y += w0 * u0.y; a1.z += w0 * u0.z; a1.w += w0 * u0.w;
            a1.x += w1 * u1.x; a1.y += w1 * u1.y; a1.z += w1 * u1.z; a1.w += w1 * u1.w;
        }
    }
    if (k < e) {
        int s0 = srcIdx[k];
        float w0 = enorm[k];
        float4 v0 = in[s0 * F4 + lane];
        a0.x += w0 * v0.x; a0.y += w0 * v0.y; a0.z += w0 * v0.z; a0.w += w0 * v0.w;
        if (two) {
            float4 u0 = in[s0 * F4 + 32 + lane];
            a1.x += w0 * u0.x; a1.y += w0 * u0.y; a1.z += w0 * u0.z; a1.w += w0 * u0.w;
        }
    }
    out[node * F4 + lane] = a0;
    if (two) out[node * F4 + 32 + lane] = a1;
}

// ---------------- bf16 split GEMM (hi+mid, 3 MMAs) + fused BN ----------------
// out[:, colOff + 0..Cc) = A_p @ W_p^T + b_p (then BN); p = blockIdx.y.
// Block 64x64, 8 warps (4M x 2N), warp tile 16x32, K chunked by 32, double-buffered.
// a ~= a_hi + a_mid (bf16 each); D += ah*bh + ah*bm + am*bh.

__device__ __forceinline__ unsigned pk_bf2(float x, float y) {
    __nv_bfloat162 p = __floats2bfloat162_rn(x, y);
    return *reinterpret_cast<unsigned*>(&p);
}

__device__ __forceinline__ void mma_bf16(float* d, unsigned a0, unsigned a1,
                                         unsigned a2, unsigned a3,
                                         unsigned b0, unsigned b1) {
    asm volatile("mma.sync.aligned.m16n8k16.row.col.f32.bf16.bf16.f32 "
                 "{%0,%1,%2,%3}, {%4,%5,%6,%7}, {%8,%9}, {%0,%1,%2,%3};"
                 : "+f"(d[0]), "+f"(d[1]), "+f"(d[2]), "+f"(d[3])
                 : "r"(a0), "r"(a1), "r"(a2), "r"(a3), "r"(b0), "r"(b1));
}

__device__ __forceinline__ void ldg_tile(const float* __restrict__ base, int row0,
                                         int rows_max, int K, int kb, int tid,
                                         float2 v[4]) {
    #pragma unroll
    for (int it = 0; it < 4; it++) {
        int idx = tid + it * 256;
        int r = idx >> 4, j = idx & 15;
        int gr = row0 + r, gk = kb + 2 * j;
        v[it] = (gr < rows_max && gk < K)
                ? *reinterpret_cast<const float2*>(&base[(size_t)gr * K + gk])
                : make_float2(0.f, 0.f);
    }
}

__device__ __forceinline__ void sts_tile(unsigned (*buf)[36], int tid, const float2 v[4]) {
    #pragma unroll
    for (int it = 0; it < 4; it++) {
        int idx = tid + it * 256;
        int r = idx >> 4, j = idx & 15;
        float2 a = v[it];
        __nv_bfloat16 hx = __float2bfloat16_rn(a.x);
        __nv_bfloat16 hy = __float2bfloat16_rn(a.y);
        float mx = a.x - __bfloat162float(hx);
        float my = a.y - __bfloat162float(hy);
        __nv_bfloat162 hp; hp.x = hx; hp.y = hy;
        unsigned hi = *reinterpret_cast<unsigned*>(&hp);
        unsigned mid = pk_bf2(mx, my);
        uint2 val = make_uint2(hi, mid);
        *reinterpret_cast<uint2*>(&buf[r][2 * j]) = val;
    }
}

template <bool BN>
__global__ void __launch_bounds__(256)
gemm_bf16x3(const float* __restrict__ A0, const float* __restrict__ A1,
            const float* __restrict__ A2,
            const float* __restrict__ W, const float* __restrict__ bias,
            const float* __restrict__ bng, const float* __restrict__ bnb,
            const float* __restrict__ bnm, const float* __restrict__ bnv,
            float* __restrict__ out, int N, int K, int Cc, int ldOut) {
    const int p = blockIdx.y;
    const float* A  = (p == 0) ? A0 : ((p == 1) ? A1 : A2);
    const float* Wp = W + p * Cc * K;
    const float* bp = bias + p * Cc;
    const int colOff = p * Cc;

    // [buf][row][2*pair(+1)]: interleaved (hi,mid) u32 pairs; stride 36 -> conflict-free
    __shared__ unsigned sA[2][64][36];
    __shared__ unsigned sW[2][64][36];

    const int tid  = threadIdx.x;
    const int lane = tid & 31;
    const int wid  = tid >> 5;
    const int warpM = wid & 3;
    const int warpN = wid >> 2;
    const int row0 = blockIdx.x * 64;
    const int g = lane >> 2;
    const int t = lane & 3;
    const int ar = warpM * 16 + g;

    float acc[4][4];
    #pragma unroll
    for (int nt = 0; nt < 4; nt++)
        #pragma unroll
        for (int j = 0; j < 4; j++) acc[nt][j] = 0.0f;

    float2 aReg[4], wReg[4];
    ldg_tile(A, row0, N, K, 0, tid, aReg);
    ldg_tile(Wp, 0, Cc, K, 0, tid, wReg);
    sts_tile(sA[0], tid, aReg);
    sts_tile(sW[0], tid, wReg);
    __syncthreads();

    const int nC = (K + 31) / 32;
    for (int c = 0; c < nC; c++) {
        const int cur = c & 1;
        if (c + 1 < nC) {
            ldg_tile(A, row0, N, K, (c + 1) * 32, tid, aReg);
            ldg_tile(Wp, 0, Cc, K, (c + 1) * 32, tid, wReg);
        }
        #pragma unroll
        for (int ks = 0; ks < 2; ks++) {
            const int pb = 2 * (8 * ks + t);
            uint2 a0 = *reinterpret_cast<const uint2*>(&sA[cur][ar][pb]);
            uint2 a1 = *reinterpret_cast<const uint2*>(&sA[cur][ar + 8][pb]);
            uint2 a2 = *reinterpret_cast<const uint2*>(&sA[cur][ar][pb + 8]);
            uint2 a3 = *reinterpret_cast<const uint2*>(&sA[cur][ar + 8][pb + 8]);
            #pragma unroll
            for (int nt = 0; nt < 4; nt++) {
                const int bn_ = warpN * 32 + nt * 8 + g;
                uint2 b0 = *reinterpret_cast<const uint2*>(&sW[cur][bn_][pb]);
                uint2 b1 = *reinterpret_cast<const uint2*>(&sW[cur][bn_][pb + 8]);
                mma_bf16(acc[nt], a0.x, a1.x, a2.x, a3.x, b0.x, b1.x);  // hi*hi
                mma_bf16(acc[nt], a0.x, a1.x, a2.x, a3.x, b0.y, b1.y);  // hi*mid
                mma_bf16(acc[nt], a0.y, a1.y, a2.y, a3.y, b0.x, b1.x);  // mid*hi
            }
        }
        if (c + 1 < nC) {
            sts_tile(sA[(c + 1) & 1], tid, aReg);
            sts_tile(sW[(c + 1) & 1], tid, wReg);
        }
        __syncthreads();
    }

    // epilogue: bias + optional BN fold
    const int rlo = row0 + warpM * 16 + g;
    #pragma unroll
    for (int nt = 0; nt < 4; nt++) {
        const int cb = warpN * 32 + nt * 8 + 2 * t;
        #pragma unroll
        for (int jj = 0; jj < 2; jj++) {
            int c = cb + jj;
            if (c >= Cc) continue;
            float add = bp[c];
            float scale = 1.0f, shift = 0.0f;
            if (BN) {
                int cg = colOff + c;
                scale = bng[cg] * rsqrtf(bnv[cg] + BN_EPS);
                shift = bnb[cg] - bnm[cg] * scale;
            }
            float v0 = acc[nt][jj] + add;
            float v1 = acc[nt][2 + jj] + add;
            if (BN) { v0 = v0 * scale + shift; v1 = v1 * scale + shift; }
            if (rlo < N)     out[(size_t)rlo * ldOut + colOff + c] = v0;
            if (rlo + 8 < N) out[(size_t)(rlo + 8) * ldOut + colOff + c] = v1;
        }
    }
}

// ---------------- host launch ----------------
extern "C" void kernel_launch(void* const* d_in, const int* in_sizes, int n_in,
                              void* d_out, int out_size) {
    const float* x       = (const float*)d_in[0];
    const int*   ei      = (const int*)d_in[1];
    const float* conv1_W = (const float*)d_in[2];
    const float* conv1_b = (const float*)d_in[3];
    const float* conv2_W = (const float*)d_in[4];
    const float* conv2_b = (const float*)d_in[5];
    const float* conv3_W = (const float*)d_in[6];
    const float* conv3_b = (const float*)d_in[7];
    const float* bn1_g = (const float*)d_in[8];
    const float* bn1_b = (const float*)d_in[9];
    const float* bn1_m = (const float*)d_in[10];
    const float* bn1_v = (const float*)d_in[11];
    const float* bn2_g = (const float*)d_in[12];
    const float* bn2_b = (const float*)d_in[13];
    const float* bn2_m = (const float*)d_in[14];
    const float* bn2_v = (const float*)d_in[15];
    const float* bn3_g = (const float*)d_in[16];
    const float* bn3_b = (const float*)d_in[17];
    const float* bn3_m = (const float*)d_in[18];
    const float* bn3_v = (const float*)d_in[19];
    const float* lin_W = (const float*)d_in[20];
    const float* lin_b = (const float*)d_in[21];
    float* out = (float*)d_out;

    const int N = in_sizes[0] / DD;
    const int E = in_sizes[1] / 2;

    float *T1, *T2, *Ha, *Hb, *enorm, *dis;
    int *cnt, *ptr, *cursor, *srcIdx;
    cudaGetSymbolAddress((void**)&T1, g_T1);
    cudaGetSymbolAddress((void**)&T2, g_T2);
    cudaGetSymbolAddress((void**)&Ha, g_Ha);
    cudaGetSymbolAddress((void**)&Hb, g_Hb);
    cudaGetSymbolAddress((void**)&cnt, g_cnt);
    cudaGetSymbolAddress((void**)&ptr, g_ptr);
    cudaGetSymbolAddress((void**)&cursor, g_cursor);
    cudaGetSymbolAddress((void**)&srcIdx, g_srcIdx);
    cudaGetSymbolAddress((void**)&enorm, g_enorm);
    cudaGetSymbolAddress((void**)&dis, g_dis);

    const int* e_row = ei;
    const int* e_col = ei + E;

    // ---- CSR build ----
    cudaMemsetAsync(cnt, 0, N * sizeof(int));
    hist_kernel<<<(E + 255) / 256, 256>>>(e_col, cnt, E);
    dis_kernel<<<(N + 255) / 256, 256>>>(cnt, dis, N);
    scan_kernel<<<1, 1024>>>(cnt, ptr, cursor, N);
    scatter_kernel<<<(E + 255) / 256, 256>>>(e_row, e_col, dis, cursor, srcIdx, enorm, E);

    dim3 gemmGrid3((N + 63) / 64, 3);
    dim3 gemmGrid1((N + 63) / 64, 1);
    const int spmmBlocks = (N + 7) / 8;

    // ---- layer 1 (K = 128) ----
    spmm_v2<32><<<spmmBlocks, 256>>>((const float4*)x, (float4*)T1, ptr, srcIdx, enorm, dis, N);
    spmm_v2<32><<<spmmBlocks, 256>>>((const float4*)T1, (float4*)T2, ptr, srcIdx, enorm, dis, N);
    gemm_bf16x3<true><<<gemmGrid3, 256>>>(x, T1, T2, conv1_W, conv1_b,
                                          bn1_g, bn1_b, bn1_m, bn1_v,
                                          Ha, N, DD, HH, H3);

    // ---- layer 2 (K = 180) ----
    spmm_v2<45><<<spmmBlocks, 256>>>((const float4*)Ha, (float4*)T1, ptr, srcIdx, enorm, dis, N);
    spmm_v2<45><<<spmmBlocks, 256>>>((const float4*)T1, (float4*)T2, ptr, srcIdx, enorm, dis, N);
    gemm_bf16x3<true><<<gemmGrid3, 256>>>(Ha, T1, T2, conv2_W, conv2_b,
                                          bn2_g, bn2_b, bn2_m, bn2_v,
                                          Hb, N, H3, HH, H3);

    // ---- layer 3 (K = 180) ----
    spmm_v2<45><<<spmmBlocks, 256>>>((const float4*)Hb, (float4*)T1, ptr, srcIdx, enorm, dis, N);
    spmm_v2<45><<<spmmBlocks, 256>>>((const float4*)T1, (float4*)T2, ptr, srcIdx, enorm, dis, N);
    gemm_bf16x3<true><<<gemmGrid3, 256>>>(Hb, T1, T2, conv3_W, conv3_b,
                                          bn3_g, bn3_b, bn3_m, bn3_v,
                                          Ha, N, H3, HH, H3);

    // ---- final linear (no BN) ----
    gemm_bf16x3<false><<<gemmGrid1, 256>>>(Ha, Ha, Ha, lin_W, lin_b,
                                           nullptr, nullptr, nullptr, nullptr,
                                           out, N, H3, CC, CC);
}

// round 6
// speedup vs baseline: 2.1054x; 1.0664x over previous
#include <cuda_runtime.h>
#include <cuda_bf16.h>

// ---------------- problem constants ----------------
#define NN 50000
#define EE 400000
#define DD 128
#define HH 60
#define H3 180
#define CC 40
#define BN_EPS 1e-5f

// ---------------- static scratch ----------------
__device__ float g_Zr[NN * 120];   // raw p=1,2 projections (then hop-1 raw p=2)
__device__ float g_Zs[NN * 60];    // raw hop-1 result for p=2
__device__ float g_Ha[NN * H3];
__device__ float g_Hb[NN * H3];
__device__ float g_scale[3 * H3];  // folded BN scale per layer/channel
__device__ float g_shift[3 * H3];  // folded conv-bias + BN shift
__device__ int   g_cnt[NN];
__device__ int   g_ptr[NN + 1];
__device__ int   g_cursor[NN];
__device__ int   g_srcIdx[EE];
__device__ float g_enorm[EE];
__device__ float g_dis[NN];

// ---------------- CSR build ----------------
__global__ void hist_kernel(const int* __restrict__ col, int* __restrict__ cnt, int E) {
    int e = blockIdx.x * blockDim.x + threadIdx.x;
    if (e < E) atomicAdd(&cnt[col[e]], 1);
}

__global__ void dis_kernel(const int* __restrict__ cnt, float* __restrict__ dis, int n) {
    int i = blockIdx.x * blockDim.x + threadIdx.x;
    if (i < n) dis[i] = rsqrtf((float)(cnt[i] + 1));  // +1 self loop
}

// single-block shuffle-based exclusive scan
__global__ void scan_kernel(const int* __restrict__ cnt, int* __restrict__ ptr,
                            int* __restrict__ cursor, int n) {
    __shared__ int wincl[32];
    const int tid = threadIdx.x, lane = tid & 31, wid = tid >> 5;
    int carry = 0;
    for (int base = 0; base < n; base += 1024) {
        int i = base + tid;
        int v = (i < n) ? cnt[i] : 0;
        int x = v;
        #pragma unroll
        for (int off = 1; off < 32; off <<= 1) {
            int t = __shfl_up_sync(0xffffffffu, x, off);
            if (lane >= off) x += t;
        }
        if (lane == 31) wincl[wid] = x;
        __syncthreads();
        if (wid == 0) {
            int w = wincl[lane];
            #pragma unroll
            for (int off = 1; off < 32; off <<= 1) {
                int t = __shfl_up_sync(0xffffffffu, w, off);
                if (lane >= off) w += t;
            }
            wincl[lane] = w;
        }
        __syncthreads();
        int woff = wid ? wincl[wid - 1] : 0;
        int excl = carry + woff + x - v;
        if (i < n) { ptr[i] = excl; cursor[i] = excl; }
        carry += wincl[31];
        __syncthreads();
    }
    if (tid == 0) ptr[n] = carry;
}

__global__ void scatter_kernel(const int* __restrict__ row, const int* __restrict__ col,
                               const float* __restrict__ dis, int* __restrict__ cursor,
                               int* __restrict__ srcIdx, float* __restrict__ enorm, int E) {
    int e = blockIdx.x * blockDim.x + threadIdx.x;
    if (e < E) {
        int r = row[e], c = col[e];
        int pos = atomicAdd(&cursor[c], 1);
        srcIdx[pos] = r;
        enorm[pos]  = dis[r] * dis[c];
    }
}

// ---------------- folded BN scale/shift precompute ----------------
// final = ((z + conv_b) - m) * g / sqrt(v+eps) + b  =  z*scale + shift
__global__ void ss_kernel(const float* __restrict__ convb, const float* __restrict__ g,
                          const float* __restrict__ b, const float* __restrict__ m,
                          const float* __restrict__ v,
                          float* __restrict__ sc, float* __restrict__ sh) {
    int c = threadIdx.x;
    if (c < H3) {
        float s = g[c] * rsqrtf(v[c] + BN_EPS);
        sc[c] = s;
        sh[c] = (convb[c] - m[c]) * s + b[c];
    }
}

// ---------------- SpMM hop 1: 120-wide; finalize p=1 block, raw p=2 block ----
// agg[i] = dis[i]^2 * Zr[i] + sum enorm * Zr[src]
// cols 0:60  -> H[i, 60:120]  with scale/shift (ss pointers at region base)
// cols 60:120 -> Zs[i, 0:60]  raw
__global__ void __launch_bounds__(256)
spmm_h1(const float4* __restrict__ Zr, float4* __restrict__ H, float4* __restrict__ Zs,
        const int* __restrict__ ptr, const int* __restrict__ srcIdx,
        const float* __restrict__ enorm, const float* __restrict__ dis,
        const float* __restrict__ ssS, const float* __restrict__ ssH, int N) {
    const int lane = threadIdx.x & 31;
    const int node = blockIdx.x * 8 + (threadIdx.x >> 5);
    if (node >= N) return;
    const bool act = lane < 30;

    float d = dis[node];
    float dd = d * d;
    float4 acc = make_float4(0.f, 0.f, 0.f, 0.f);
    if (act) {
        float4 v = Zr[node * 30 + lane];
        acc.x = dd * v.x; acc.y = dd * v.y; acc.z = dd * v.z; acc.w = dd * v.w;
    }

    int s = ptr[node], e = ptr[node + 1];
    int k = s;
    for (; k + 1 < e; k += 2) {
        int s0 = srcIdx[k], s1 = srcIdx[k + 1];
        float w0 = enorm[k], w1 = enorm[k + 1];
        if (act) {
            float4 v0 = Zr[s0 * 30 + lane];
            float4 v1 = Zr[s1 * 30 + lane];
            acc.x += w0 * v0.x; acc.y += w0 * v0.y; acc.z += w0 * v0.z; acc.w += w0 * v0.w;
            acc.x += w1 * v1.x; acc.y += w1 * v1.y; acc.z += w1 * v1.z; acc.w += w1 * v1.w;
        }
    }
    if (k < e) {
        int s0 = srcIdx[k];
        float w0 = enorm[k];
        if (act) {
            float4 v0 = Zr[s0 * 30 + lane];
            acc.x += w0 * v0.x; acc.y += w0 * v0.y; acc.z += w0 * v0.z; acc.w += w0 * v0.w;
        }
    }

    if (lane < 15) {
        float4 sc = reinterpret_cast<const float4*>(ssS)[lane];
        float4 sh = reinterpret_cast<const float4*>(ssH)[lane];
        float4 o;
        o.x = acc.x * sc.x + sh.x;
        o.y = acc.y * sc.y + sh.y;
        o.z = acc.z * sc.z + sh.z;
        o.w = acc.w * sc.w + sh.w;
        H[node * 45 + 15 + lane] = o;       // H[:, 60:120]
    } else if (act) {
        Zs[node * 15 + (lane - 15)] = acc;  // raw p=2 hop-1
    }
}

// ---------------- SpMM hop 2: 60-wide; finalize p=2 block ----
__global__ void __launch_bounds__(256)
spmm_h2(const float4* __restrict__ Zs, float4* __restrict__ H,
        const int* __restrict__ ptr, const int* __restrict__ srcIdx,
        const float* __restrict__ enorm, const float* __restrict__ dis,
        const float* __restrict__ ssS, const float* __restrict__ ssH, int N) {
    const int l = threadIdx.x & 15;
    const int node = blockIdx.x * 16 + (threadIdx.x >> 4);
    if (node >= N) return;
    const bool act = l < 15;

    float d = dis[node];
    float dd = d * d;
    float4 acc = make_float4(0.f, 0.f, 0.f, 0.f);
    if (act) {
        float4 v = Zs[node * 15 + l];
        acc.x = dd * v.x; acc.y = dd * v.y; acc.z = dd * v.z; acc.w = dd * v.w;
    }

    int s = ptr[node], e = ptr[node + 1];
    int k = s;
    for (; k + 1 < e; k += 2) {
        int s0 = srcIdx[k], s1 = srcIdx[k + 1];
        float w0 = enorm[k], w1 = enorm[k + 1];
        if (act) {
            float4 v0 = Zs[s0 * 15 + l];
            float4 v1 = Zs[s1 * 15 + l];
            acc.x += w0 * v0.x; acc.y += w0 * v0.y; acc.z += w0 * v0.z; acc.w += w0 * v0.w;
            acc.x += w1 * v1.x; acc.y += w1 * v1.y; acc.z += w1 * v1.z; acc.w += w1 * v1.w;
        }
    }
    if (k < e) {
        int s0 = srcIdx[k];
        float w0 = enorm[k];
        if (act) {
            float4 v0 = Zs[s0 * 15 + l];
            acc.x += w0 * v0.x; acc.y += w0 * v0.y; acc.z += w0 * v0.z; acc.w += w0 * v0.w;
        }
    }

    if (act) {
        float4 sc = reinterpret_cast<const float4*>(ssS)[l];
        float4 sh = reinterpret_cast<const float4*>(ssH)[l];
        float4 o;
        o.x = acc.x * sc.x + sh.x;
        o.y = acc.y * sc.y + sh.y;
        o.z = acc.z * sc.z + sh.z;
        o.w = acc.w * sc.w + sh.w;
        H[node * 45 + 30 + l] = o;          // H[:, 120:180]
    }
}

// ---------------- bf16 split GEMM (hi+mid, 3 MMAs) ----------------
__device__ __forceinline__ unsigned pk_bf2(float x, float y) {
    __nv_bfloat162 p = __floats2bfloat162_rn(x, y);
    return *reinterpret_cast<unsigned*>(&p);
}

__device__ __forceinline__ void mma_bf16(float* d, unsigned a0, unsigned a1,
                                         unsigned a2, unsigned a3,
                                         unsigned b0, unsigned b1) {
    asm volatile("mma.sync.aligned.m16n8k16.row.col.f32.bf16.bf16.f32 "
                 "{%0,%1,%2,%3}, {%4,%5,%6,%7}, {%8,%9}, {%0,%1,%2,%3};"
                 : "+f"(d[0]), "+f"(d[1]), "+f"(d[2]), "+f"(d[3])
                 : "r"(a0), "r"(a1), "r"(a2), "r"(a3), "r"(b0), "r"(b1));
}

__device__ __forceinline__ void ldg_tile(const float* __restrict__ base, int row0,
                                         int rows_max, int K, int kb, int tid,
                                         float2 v[4]) {
    #pragma unroll
    for (int it = 0; it < 4; it++) {
        int idx = tid + it * 256;
        int r = idx >> 4, j = idx & 15;
        int gr = row0 + r, gk = kb + 2 * j;
        v[it] = (gr < rows_max && gk < K)
                ? *reinterpret_cast<const float2*>(&base[(size_t)gr * K + gk])
                : make_float2(0.f, 0.f);
    }
}

__device__ __forceinline__ void sts_tile(unsigned (*buf)[36], int tid, const float2 v[4]) {
    #pragma unroll
    for (int it = 0; it < 4; it++) {
        int idx = tid + it * 256;
        int r = idx >> 4, j = idx & 15;
        float2 a = v[it];
        __nv_bfloat16 hx = __float2bfloat16_rn(a.x);
        __nv_bfloat16 hy = __float2bfloat16_rn(a.y);
        float mx = a.x - __bfloat162float(hx);
        float my = a.y - __bfloat162float(hy);
        __nv_bfloat162 hp; hp.x = hx; hp.y = hy;
        unsigned hi = *reinterpret_cast<unsigned*>(&hp);
        unsigned mid = pk_bf2(mx, my);
        *reinterpret_cast<uint2*>(&buf[r][2 * j]) = make_uint2(hi, mid);
    }
}

// CONV: grid.y = 3 powers over the SAME A; p=0 finalized into Hdst[:,0:60],
//       p=1,2 raw into Zr[:,(p-1)*60 ..]. !CONV: final linear, bias only.
template <bool CONV>
__global__ void __launch_bounds__(256)
gemm_bf16x3(const float* __restrict__ A, const float* __restrict__ W,
            const float* __restrict__ bias,
            const float* __restrict__ ssS, const float* __restrict__ ssH,
            float* __restrict__ Hdst, float* __restrict__ Zr,
            float* __restrict__ outF, int N, int K, int Cc) {
    const int p = CONV ? blockIdx.y : 0;
    const float* Wp = W + p * Cc * K;

    __shared__ unsigned sA[2][64][36];
    __shared__ unsigned sW[2][64][36];

    const int tid  = threadIdx.x;
    const int lane = tid & 31;
    const int wid  = tid >> 5;
    const int warpM = wid & 3;
    const int warpN = wid >> 2;
    const int row0 = blockIdx.x * 64;
    const int g = lane >> 2;
    const int t = lane & 3;
    const int ar = warpM * 16 + g;

    float acc[4][4];
    #pragma unroll
    for (int nt = 0; nt < 4; nt++)
        #pragma unroll
        for (int j = 0; j < 4; j++) acc[nt][j] = 0.0f;

    float2 aReg[4], wReg[4];
    ldg_tile(A, row0, N, K, 0, tid, aReg);
    ldg_tile(Wp, 0, Cc, K, 0, tid, wReg);
    sts_tile(sA[0], tid, aReg);
    sts_tile(sW[0], tid, wReg);
    __syncthreads();

    const int nC = (K + 31) / 32;
    for (int c = 0; c < nC; c++) {
        const int cur = c & 1;
        if (c + 1 < nC) {
            ldg_tile(A, row0, N, K, (c + 1) * 32, tid, aReg);
            ldg_tile(Wp, 0, Cc, K, (c + 1) * 32, tid, wReg);
        }
        #pragma unroll
        for (int ks = 0; ks < 2; ks++) {
            const int pb = 2 * (8 * ks + t);
            uint2 a0 = *reinterpret_cast<const uint2*>(&sA[cur][ar][pb]);
            uint2 a1 = *reinterpret_cast<const uint2*>(&sA[cur][ar + 8][pb]);
            uint2 a2 = *reinterpret_cast<const uint2*>(&sA[cur][ar][pb + 8]);
            uint2 a3 = *reinterpret_cast<const uint2*>(&sA[cur][ar + 8][pb + 8]);
            #pragma unroll
            for (int nt = 0; nt < 4; nt++) {
                const int bn_ = warpN * 32 + nt * 8 + g;
                uint2 b0 = *reinterpret_cast<const uint2*>(&sW[cur][bn_][pb]);
                uint2 b1 = *reinterpret_cast<const uint2*>(&sW[cur][bn_][pb + 8]);
                mma_bf16(acc[nt], a0.x, a1.x, a2.x, a3.x, b0.x, b1.x);  // hi*hi
                mma_bf16(acc[nt], a0.x, a1.x, a2.x, a3.x, b0.y, b1.y);  // hi*mid
                mma_bf16(acc[nt], a0.y, a1.y, a2.y, a3.y, b0.x, b1.x);  // mid*hi
            }
        }
        if (c + 1 < nC) {
            sts_tile(sA[(c + 1) & 1], tid, aReg);
            sts_tile(sW[(c + 1) & 1], tid, wReg);
        }
        __syncthreads();
    }

    const int rlo = row0 + warpM * 16 + g;
    #pragma unroll
    for (int nt = 0; nt < 4; nt++) {
        const int cb = warpN * 32 + nt * 8 + 2 * t;
        #pragma unroll
        for (int jj = 0; jj < 2; jj++) {
            int c = cb + jj;
            if (c >= Cc) continue;
            float v0 = acc[nt][jj];
            float v1 = acc[nt][2 + jj];
            if (CONV) {
                if (p == 0) {
                    float sc = ssS[c], sh = ssH[c];
                    if (rlo < N)     Hdst[(size_t)rlo * H3 + c] = v0 * sc + sh;
                    if (rlo + 8 < N) Hdst[(size_t)(rlo + 8) * H3 + c] = v1 * sc + sh;
                } else {
                    int zc = (p - 1) * 60 + c;
                    if (rlo < N)     Zr[(size_t)rlo * 120 + zc] = v0;
                    if (rlo + 8 < N) Zr[(size_t)(rlo + 8) * 120 + zc] = v1;
                }
            } else {
                float add = bias[c];
                if (rlo < N)     outF[(size_t)rlo * CC + c] = v0 + add;
                if (rlo + 8 < N) outF[(size_t)(rlo + 8) * CC + c] = v1 + add;
            }
        }
    }
}

// ---------------- host launch ----------------
extern "C" void kernel_launch(void* const* d_in, const int* in_sizes, int n_in,
                              void* d_out, int out_size) {
    const float* x       = (const float*)d_in[0];
    const int*   ei      = (const int*)d_in[1];
    const float* conv1_W = (const float*)d_in[2];
    const float* conv1_b = (const float*)d_in[3];
    const float* conv2_W = (const float*)d_in[4];
    const float* conv2_b = (const float*)d_in[5];
    const float* conv3_W = (const float*)d_in[6];
    const float* conv3_b = (const float*)d_in[7];
    const float* bn1_g = (const float*)d_in[8];
    const float* bn1_b = (const float*)d_in[9];
    const float* bn1_m = (const float*)d_in[10];
    const float* bn1_v = (const float*)d_in[11];
    const float* bn2_g = (const float*)d_in[12];
    const float* bn2_b = (const float*)d_in[13];
    const float* bn2_m = (const float*)d_in[14];
    const float* bn2_v = (const float*)d_in[15];
    const float* bn3_g = (const float*)d_in[16];
    const float* bn3_b = (const float*)d_in[17];
    const float* bn3_m = (const float*)d_in[18];
    const float* bn3_v = (const float*)d_in[19];
    const float* lin_W = (const float*)d_in[20];
    const float* lin_b = (const float*)d_in[21];
    float* out = (float*)d_out;

    const int N = in_sizes[0] / DD;
    const int E = in_sizes[1] / 2;

    float *Zr, *Zs, *Ha, *Hb, *enorm, *dis, *sc, *sh;
    int *cnt, *ptr, *cursor, *srcIdx;
    cudaGetSymbolAddress((void**)&Zr, g_Zr);
    cudaGetSymbolAddress((void**)&Zs, g_Zs);
    cudaGetSymbolAddress((void**)&Ha, g_Ha);
    cudaGetSymbolAddress((void**)&Hb, g_Hb);
    cudaGetSymbolAddress((void**)&sc, g_scale);
    cudaGetSymbolAddress((void**)&sh, g_shift);
    cudaGetSymbolAddress((void**)&cnt, g_cnt);
    cudaGetSymbolAddress((void**)&ptr, g_ptr);
    cudaGetSymbolAddress((void**)&cursor, g_cursor);
    cudaGetSymbolAddress((void**)&srcIdx, g_srcIdx);
    cudaGetSymbolAddress((void**)&enorm, g_enorm);
    cudaGetSymbolAddress((void**)&dis, g_dis);

    const int* e_row = ei;
    const int* e_col = ei + E;

    // ---- CSR build ----
    cudaMemsetAsync(cnt, 0, N * sizeof(int));
    hist_kernel<<<(E + 255) / 256, 256>>>(e_col, cnt, E);
    dis_kernel<<<(N + 255) / 256, 256>>>(cnt, dis, N);
    scan_kernel<<<1, 1024>>>(cnt, ptr, cursor, N);
    scatter_kernel<<<(E + 255) / 256, 256>>>(e_row, e_col, dis, cursor, srcIdx, enorm, E);

    // ---- folded scale/shift per layer ----
    ss_kernel<<<1, H3>>>(conv1_b, bn1_g, bn1_b, bn1_m, bn1_v, sc,          sh);
    ss_kernel<<<1, H3>>>(conv2_b, bn2_g, bn2_b, bn2_m, bn2_v, sc + H3,     sh + H3);
    ss_kernel<<<1, H3>>>(conv3_b, bn3_g, bn3_b, bn3_m, bn3_v, sc + 2 * H3, sh + 2 * H3);

    dim3 gemmGrid3((N + 63) / 64, 3);
    dim3 gemmGrid1((N + 63) / 64, 1);
    const int h1Blocks = (N + 7) / 8;
    const int h2Blocks = (N + 15) / 16;

    // ---- layer 1: project first (K=128), then aggregate narrow ----
    gemm_bf16x3<true><<<gemmGrid3, 256>>>(x, conv1_W, nullptr, sc, sh,
                                          Ha, Zr, nullptr, N, DD, HH);
    spmm_h1<<<h1Blocks, 256>>>((const float4*)Zr, (float4*)Ha, (float4*)Zs,
                               ptr, srcIdx, enorm, dis, sc + 60, sh + 60, N);
    spmm_h2<<<h2Blocks, 256>>>((const float4*)Zs, (float4*)Ha,
                               ptr, srcIdx, enorm, dis, sc + 120, sh + 120, N);

    // ---- layer 2 (K=180) ----
    gemm_bf16x3<true><<<gemmGrid3, 256>>>(Ha, conv2_W, nullptr, sc + H3, sh + H3,
                                          Hb, Zr, nullptr, N, H3, HH);
    spmm_h1<<<h1Blocks, 256>>>((const float4*)Zr, (float4*)Hb, (float4*)Zs,
                               ptr, srcIdx, enorm, dis, sc + H3 + 60, sh + H3 + 60, N);
    spmm_h2<<<h2Blocks, 256>>>((const float4*)Zs, (float4*)Hb,
                               ptr, srcIdx, enorm, dis, sc + H3 + 120, sh + H3 + 120, N);

    // ---- layer 3 (K=180) ----
    gemm_bf16x3<true><<<gemmGrid3, 256>>>(Hb, conv3_W, nullptr, sc + 2 * H3, sh + 2 * H3,
                                          Ha, Zr, nullptr, N, H3, HH);
    spmm_h1<<<h1Blocks, 256>>>((const float4*)Zr, (float4*)Ha, (float4*)Zs,
                               ptr, srcIdx, enorm, dis, sc + 2 * H3 + 60, sh + 2 * H3 + 60, N);
    spmm_h2<<<h2Blocks, 256>>>((const float4*)Zs, (float4*)Ha,
                               ptr, srcIdx, enorm, dis, sc + 2 * H3 + 120, sh + 2 * H3 + 120, N);

    // ---- final linear ----
    gemm_bf16x3<false><<<gemmGrid1, 256>>>(Ha, lin_W, lin_b, nullptr, nullptr,
                                           nullptr, nullptr, out, N, H3, CC);
}

// round 7
// speedup vs baseline: 2.2133x; 1.0512x over previous
#include <cuda_runtime.h>
#include <cuda_bf16.h>

// ---------------- problem constants ----------------
#define NN 50000
#define EE 400000
#define DD 128
#define HH 60
#define H3 180
#define CC 40
#define BN_EPS 1e-5f

// ---------------- static scratch ----------------
__device__ float g_Zr[NN * 120];   // raw p=1,2 projections
__device__ float g_Zs[NN * 60];    // raw hop-1 result for p=2
__device__ float g_Ha[NN * H3];
__device__ float g_Hb[NN * H3];
__device__ float g_scale[3 * H3];  // folded BN scale per layer/channel
__device__ float g_shift[3 * H3];  // folded conv-bias + BN shift
__device__ int   g_cnt[NN];
__device__ int   g_ptr[NN + 1];
__device__ int   g_cursor[NN];
__device__ int   g_srcIdx[EE];
__device__ float g_enorm[EE];
__device__ float g_dis[NN];

// ---------------- CSR build ----------------
__global__ void hist_kernel(const int* __restrict__ col, int* __restrict__ cnt, int E) {
    int e = blockIdx.x * blockDim.x + threadIdx.x;
    if (e < E) atomicAdd(&cnt[col[e]], 1);
}

__global__ void dis_kernel(const int* __restrict__ cnt, float* __restrict__ dis, int n) {
    int i = blockIdx.x * blockDim.x + threadIdx.x;
    if (i < n) dis[i] = rsqrtf((float)(cnt[i] + 1));  // +1 self loop
}

// single-block shuffle-based exclusive scan
__global__ void scan_kernel(const int* __restrict__ cnt, int* __restrict__ ptr,
                            int* __restrict__ cursor, int n) {
    __shared__ int wincl[32];
    const int tid = threadIdx.x, lane = tid & 31, wid = tid >> 5;
    int carry = 0;
    for (int base = 0; base < n; base += 1024) {
        int i = base + tid;
        int v = (i < n) ? cnt[i] : 0;
        int x = v;
        #pragma unroll
        for (int off = 1; off < 32; off <<= 1) {
            int t = __shfl_up_sync(0xffffffffu, x, off);
            if (lane >= off) x += t;
        }
        if (lane == 31) wincl[wid] = x;
        __syncthreads();
        if (wid == 0) {
            int w = wincl[lane];
            #pragma unroll
            for (int off = 1; off < 32; off <<= 1) {
                int t = __shfl_up_sync(0xffffffffu, w, off);
                if (lane >= off) w += t;
            }
            wincl[lane] = w;
        }
        __syncthreads();
        int woff = wid ? wincl[wid - 1] : 0;
        int excl = carry + woff + x - v;
        if (i < n) { ptr[i] = excl; cursor[i] = excl; }
        carry += wincl[31];
        __syncthreads();
    }
    if (tid == 0) ptr[n] = carry;
}

__global__ void scatter_kernel(const int* __restrict__ row, const int* __restrict__ col,
                               const float* __restrict__ dis, int* __restrict__ cursor,
                               int* __restrict__ srcIdx, float* __restrict__ enorm, int E) {
    int e = blockIdx.x * blockDim.x + threadIdx.x;
    if (e < E) {
        int r = row[e], c = col[e];
        int pos = atomicAdd(&cursor[c], 1);
        srcIdx[pos] = r;
        enorm[pos]  = dis[r] * dis[c];
    }
}

// ---------------- folded BN scale/shift precompute (one launch, 3 blocks) ----
__global__ void ss_all_kernel(const float* __restrict__ b1c, const float* __restrict__ g1,
                              const float* __restrict__ b1, const float* __restrict__ m1,
                              const float* __restrict__ v1,
                              const float* __restrict__ b2c, const float* __restrict__ g2,
                              const float* __restrict__ b2, const float* __restrict__ m2,
                              const float* __restrict__ v2,
                              const float* __restrict__ b3c, const float* __restrict__ g3,
                              const float* __restrict__ b3, const float* __restrict__ m3,
                              const float* __restrict__ v3,
                              float* __restrict__ sc, float* __restrict__ sh) {
    int L = blockIdx.x;
    int c = threadIdx.x;
    if (c >= H3) return;
    const float* cb = (L == 0) ? b1c : (L == 1) ? b2c : b3c;
    const float* g  = (L == 0) ? g1  : (L == 1) ? g2  : g3;
    const float* b  = (L == 0) ? b1  : (L == 1) ? b2  : b3;
    const float* m  = (L == 0) ? m1  : (L == 1) ? m2  : m3;
    const float* v  = (L == 0) ? v1  : (L == 1) ? v2  : v3;
    float s = g[c] * rsqrtf(v[c] + BN_EPS);
    sc[L * H3 + c] = s;
    sh[L * H3 + c] = (cb[c] - m[c]) * s + b[c];
}

// ---------------- SpMM hop 1: 120-wide; finalize p=1 block, raw p=2 block ----
__global__ void __launch_bounds__(256)
spmm_h1(const float4* __restrict__ Zr, float4* __restrict__ H, float4* __restrict__ Zs,
        const int* __restrict__ ptr, const int* __restrict__ srcIdx,
        const float* __restrict__ enorm, const float* __restrict__ dis,
        const float* __restrict__ ssS, const float* __restrict__ ssH, int N) {
    const int lane = threadIdx.x & 31;
    const int node = blockIdx.x * 8 + (threadIdx.x >> 5);
    if (node >= N) return;
    const bool act = lane < 30;

    float d = dis[node];
    float dd = d * d;
    float4 acc = make_float4(0.f, 0.f, 0.f, 0.f);
    if (act) {
        float4 v = Zr[node * 30 + lane];
        acc.x = dd * v.x; acc.y = dd * v.y; acc.z = dd * v.z; acc.w = dd * v.w;
    }

    int s = ptr[node], e = ptr[node + 1];
    int k = s;
    for (; k + 1 < e; k += 2) {
        int s0 = srcIdx[k], s1 = srcIdx[k + 1];
        float w0 = enorm[k], w1 = enorm[k + 1];
        if (act) {
            float4 v0 = Zr[s0 * 30 + lane];
            float4 v1 = Zr[s1 * 30 + lane];
            acc.x += w0 * v0.x; acc.y += w0 * v0.y; acc.z += w0 * v0.z; acc.w += w0 * v0.w;
            acc.x += w1 * v1.x; acc.y += w1 * v1.y; acc.z += w1 * v1.z; acc.w += w1 * v1.w;
        }
    }
    if (k < e) {
        int s0 = srcIdx[k];
        float w0 = enorm[k];
        if (act) {
            float4 v0 = Zr[s0 * 30 + lane];
            acc.x += w0 * v0.x; acc.y += w0 * v0.y; acc.z += w0 * v0.z; acc.w += w0 * v0.w;
        }
    }

    if (lane < 15) {
        float4 sc = reinterpret_cast<const float4*>(ssS)[lane];
        float4 sh = reinterpret_cast<const float4*>(ssH)[lane];
        float4 o;
        o.x = acc.x * sc.x + sh.x;
        o.y = acc.y * sc.y + sh.y;
        o.z = acc.z * sc.z + sh.z;
        o.w = acc.w * sc.w + sh.w;
        H[node * 45 + 15 + lane] = o;       // H[:, 60:120]
    } else if (act) {
        Zs[node * 15 + (lane - 15)] = acc;  // raw p=2 hop-1
    }
}

// ---------------- SpMM hop 2: 60-wide; finalize p=2 block ----
__global__ void __launch_bounds__(256)
spmm_h2(const float4* __restrict__ Zs, float4* __restrict__ H,
        const int* __restrict__ ptr, const int* __restrict__ srcIdx,
        const float* __restrict__ enorm, const float* __restrict__ dis,
        const float* __restrict__ ssS, const float* __restrict__ ssH, int N) {
    const int l = threadIdx.x & 15;
    const int node = blockIdx.x * 16 + (threadIdx.x >> 4);
    if (node >= N) return;
    const bool act = l < 15;

    float d = dis[node];
    float dd = d * d;
    float4 acc = make_float4(0.f, 0.f, 0.f, 0.f);
    if (act) {
        float4 v = Zs[node * 15 + l];
        acc.x = dd * v.x; acc.y = dd * v.y; acc.z = dd * v.z; acc.w = dd * v.w;
    }

    int s = ptr[node], e = ptr[node + 1];
    int k = s;
    for (; k + 1 < e; k += 2) {
        int s0 = srcIdx[k], s1 = srcIdx[k + 1];
        float w0 = enorm[k], w1 = enorm[k + 1];
        if (act) {
            float4 v0 = Zs[s0 * 15 + l];
            float4 v1 = Zs[s1 * 15 + l];
            acc.x += w0 * v0.x; acc.y += w0 * v0.y; acc.z += w0 * v0.z; acc.w += w0 * v0.w;
            acc.x += w1 * v1.x; acc.y += w1 * v1.y; acc.z += w1 * v1.z; acc.w += w1 * v1.w;
        }
    }
    if (k < e) {
        int s0 = srcIdx[k];
        float w0 = enorm[k];
        if (act) {
            float4 v0 = Zs[s0 * 15 + l];
            acc.x += w0 * v0.x; acc.y += w0 * v0.y; acc.z += w0 * v0.z; acc.w += w0 * v0.w;
        }
    }

    if (act) {
        float4 sc = reinterpret_cast<const float4*>(ssS)[l];
        float4 sh = reinterpret_cast<const float4*>(ssH)[l];
        float4 o;
        o.x = acc.x * sc.x + sh.x;
        o.y = acc.y * sc.y + sh.y;
        o.z = acc.z * sc.z + sh.z;
        o.w = acc.w * sc.w + sh.w;
        H[node * 45 + 30 + l] = o;          // H[:, 120:180]
    }
}

// ---------------- bf16 split GEMM (hi+mid, 3 MMAs), 128x64 tile ----------------
__device__ __forceinline__ unsigned pk_bf2(float x, float y) {
    __nv_bfloat162 p = __floats2bfloat162_rn(x, y);
    return *reinterpret_cast<unsigned*>(&p);
}

__device__ __forceinline__ void mma_bf16(float* d, unsigned a0, unsigned a1,
                                         unsigned a2, unsigned a3,
                                         unsigned b0, unsigned b1) {
    asm volatile("mma.sync.aligned.m16n8k16.row.col.f32.bf16.bf16.f32 "
                 "{%0,%1,%2,%3}, {%4,%5,%6,%7}, {%8,%9}, {%0,%1,%2,%3};"
                 : "+f"(d[0]), "+f"(d[1]), "+f"(d[2]), "+f"(d[3])
                 : "r"(a0), "r"(a1), "r"(a2), "r"(a3), "r"(b0), "r"(b1));
}

template <int ITERS>
__device__ __forceinline__ void ldg_tile(const float* __restrict__ base, int row0,
                                         int rows_max, int K, int kb, int tid,
                                         float2 v[ITERS]) {
    #pragma unroll
    for (int it = 0; it < ITERS; it++) {
        int idx = tid + it * 256;
        int r = idx >> 4, j = idx & 15;
        int gr = row0 + r, gk = kb + 2 * j;
        v[it] = (gr < rows_max && gk < K)
                ? *reinterpret_cast<const float2*>(&base[(size_t)gr * K + gk])
                : make_float2(0.f, 0.f);
    }
}

template <int ITERS>
__device__ __forceinline__ void sts_tile(unsigned* buf, int tid, const float2 v[ITERS]) {
    #pragma unroll
    for (int it = 0; it < ITERS; it++) {
        int idx = tid + it * 256;
        int r = idx >> 4, j = idx & 15;
        float2 a = v[it];
        __nv_bfloat16 hx = __float2bfloat16_rn(a.x);
        __nv_bfloat16 hy = __float2bfloat16_rn(a.y);
        float mx = a.x - __bfloat162float(hx);
        float my = a.y - __bfloat162float(hy);
        __nv_bfloat162 hp; hp.x = hx; hp.y = hy;
        unsigned hi = *reinterpret_cast<unsigned*>(&hp);
        unsigned mid = pk_bf2(mx, my);
        *reinterpret_cast<uint2*>(&buf[r * 36 + 2 * j]) = make_uint2(hi, mid);
    }
}

#define GEMM_SMEM_BYTES ((2 * 128 * 36 + 2 * 64 * 36) * 4)

// CONV: grid.y = 3 powers over the SAME A; p=0 finalized into Hdst[:,0:60],
//       p=1,2 raw into Zr[:,(p-1)*60 ..]. !CONV: final linear, bias only.
template <bool CONV>
__global__ void __launch_bounds__(256, 2)
gemm_bf16x3(const float* __restrict__ A, const float* __restrict__ W,
            const float* __restrict__ bias,
            const float* __restrict__ ssS, const float* __restrict__ ssH,
            float* __restrict__ Hdst, float* __restrict__ Zr,
            float* __restrict__ outF, int N, int K, int Cc) {
    const int p = CONV ? blockIdx.y : 0;
    const float* Wp = W + p * Cc * K;

    extern __shared__ unsigned smem_u[];
    unsigned* sA = smem_u;                    // [2][128][36]
    unsigned* sW = smem_u + 2 * 128 * 36;     // [2][64][36]

    const int tid  = threadIdx.x;
    const int lane = tid & 31;
    const int wid  = tid >> 5;
    const int warpM = wid & 3;    // 4 x 32 rows
    const int warpN = wid >> 2;   // 2 x 32 cols
    const int row0 = blockIdx.x * 128;
    const int g = lane >> 2;
    const int t = lane & 3;
    const int mBase = warpM * 32;

    float acc[2][4][4];
    #pragma unroll
    for (int mt = 0; mt < 2; mt++)
        #pragma unroll
        for (int nt = 0; nt < 4; nt++)
            #pragma unroll
            for (int j = 0; j < 4; j++) acc[mt][nt][j] = 0.0f;

    float2 aReg[8], wReg[4];
    ldg_tile<8>(A, row0, N, K, 0, tid, aReg);
    ldg_tile<4>(Wp, 0, Cc, K, 0, tid, wReg);
    sts_tile<8>(sA, tid, aReg);
    sts_tile<4>(sW, tid, wReg);
    __syncthreads();

    const int nC = (K + 31) / 32;
    for (int c = 0; c < nC; c++) {
        const int cur = c & 1;
        const unsigned* cA = sA + cur * 128 * 36;
        const unsigned* cW = sW + cur * 64 * 36;
        if (c + 1 < nC) {
            ldg_tile<8>(A, row0, N, K, (c + 1) * 32, tid, aReg);
            ldg_tile<4>(Wp, 0, Cc, K, (c + 1) * 32, tid, wReg);
        }
        #pragma unroll
        for (int ks = 0; ks < 2; ks++) {
            const int pb = 2 * (8 * ks + t);
            uint2 aF[2][4];
            #pragma unroll
            for (int mt = 0; mt < 2; mt++) {
                const int br = mBase + mt * 16 + g;
                aF[mt][0] = *reinterpret_cast<const uint2*>(&cA[br * 36 + pb]);
                aF[mt][1] = *reinterpret_cast<const uint2*>(&cA[(br + 8) * 36 + pb]);
                aF[mt][2] = *reinterpret_cast<const uint2*>(&cA[br * 36 + pb + 8]);
                aF[mt][3] = *reinterpret_cast<const uint2*>(&cA[(br + 8) * 36 + pb + 8]);
            }
            #pragma unroll
            for (int nt = 0; nt < 4; nt++) {
                const int bn_ = warpN * 32 + nt * 8 + g;
                uint2 b0 = *reinterpret_cast<const uint2*>(&cW[bn_ * 36 + pb]);
                uint2 b1 = *reinterpret_cast<const uint2*>(&cW[bn_ * 36 + pb + 8]);
                #pragma unroll
                for (int mt = 0; mt < 2; mt++) {
                    mma_bf16(acc[mt][nt], aF[mt][0].x, aF[mt][1].x, aF[mt][2].x, aF[mt][3].x, b0.x, b1.x); // hi*hi
                    mma_bf16(acc[mt][nt], aF[mt][0].x, aF[mt][1].x, aF[mt][2].x, aF[mt][3].x, b0.y, b1.y); // hi*mid
                    mma_bf16(acc[mt][nt], aF[mt][0].y, aF[mt][1].y, aF[mt][2].y, aF[mt][3].y, b0.x, b1.x); // mid*hi
                }
            }
        }
        if (c + 1 < nC) {
            sts_tile<8>(sA + ((c + 1) & 1) * 128 * 36, tid, aReg);
            sts_tile<4>(sW + ((c + 1) & 1) * 64 * 36, tid, wReg);
        }
        __syncthreads();
    }

    #pragma unroll
    for (int mt = 0; mt < 2; mt++) {
        const int rlo = row0 + mBase + mt * 16 + g;
        #pragma unroll
        for (int nt = 0; nt < 4; nt++) {
            const int cb = warpN * 32 + nt * 8 + 2 * t;
            #pragma unroll
            for (int jj = 0; jj < 2; jj++) {
                int c = cb + jj;
                if (c >= Cc) continue;
                float v0 = acc[mt][nt][jj];
                float v1 = acc[mt][nt][2 + jj];
                if (CONV) {
                    if (p == 0) {
                        float sc = ssS[c], sh = ssH[c];
                        if (rlo < N)     Hdst[(size_t)rlo * H3 + c] = v0 * sc + sh;
                        if (rlo + 8 < N) Hdst[(size_t)(rlo + 8) * H3 + c] = v1 * sc + sh;
                    } else {
                        int zc = (p - 1) * 60 + c;
                        if (rlo < N)     Zr[(size_t)rlo * 120 + zc] = v0;
                        if (rlo + 8 < N) Zr[(size_t)(rlo + 8) * 120 + zc] = v1;
                    }
                } else {
                    float add = bias[c];
                    if (rlo < N)     outF[(size_t)rlo * CC + c] = v0 + add;
                    if (rlo + 8 < N) outF[(size_t)(rlo + 8) * CC + c] = v1 + add;
                }
            }
        }
    }
}

// ---------------- host launch ----------------
extern "C" void kernel_launch(void* const* d_in, const int* in_sizes, int n_in,
                              void* d_out, int out_size) {
    const float* x       = (const float*)d_in[0];
    const int*   ei      = (const int*)d_in[1];
    const float* conv1_W = (const float*)d_in[2];
    const float* conv1_b = (const float*)d_in[3];
    const float* conv2_W = (const float*)d_in[4];
    const float* conv2_b = (const float*)d_in[5];
    const float* conv3_W = (const float*)d_in[6];
    const float* conv3_b = (const float*)d_in[7];
    const float* bn1_g = (const float*)d_in[8];
    const float* bn1_b = (const float*)d_in[9];
    const float* bn1_m = (const float*)d_in[10];
    const float* bn1_v = (const float*)d_in[11];
    const float* bn2_g = (const float*)d_in[12];
    const float* bn2_b = (const float*)d_in[13];
    const float* bn2_m = (const float*)d_in[14];
    const float* bn2_v = (const float*)d_in[15];
    const float* bn3_g = (const float*)d_in[16];
    const float* bn3_b = (const float*)d_in[17];
    const float* bn3_m = (const float*)d_in[18];
    const float* bn3_v = (const float*)d_in[19];
    const float* lin_W = (const float*)d_in[20];
    const float* lin_b = (const float*)d_in[21];
    float* out = (float*)d_out;

    const int N = in_sizes[0] / DD;
    const int E = in_sizes[1] / 2;

    float *Zr, *Zs, *Ha, *Hb, *enorm, *dis, *sc, *sh;
    int *cnt, *ptr, *cursor, *srcIdx;
    cudaGetSymbolAddress((void**)&Zr, g_Zr);
    cudaGetSymbolAddress((void**)&Zs, g_Zs);
    cudaGetSymbolAddress((void**)&Ha, g_Ha);
    cudaGetSymbolAddress((void**)&Hb, g_Hb);
    cudaGetSymbolAddress((void**)&sc, g_scale);
    cudaGetSymbolAddress((void**)&sh, g_shift);
    cudaGetSymbolAddress((void**)&cnt, g_cnt);
    cudaGetSymbolAddress((void**)&ptr, g_ptr);
    cudaGetSymbolAddress((void**)&cursor, g_cursor);
    cudaGetSymbolAddress((void**)&srcIdx, g_srcIdx);
    cudaGetSymbolAddress((void**)&enorm, g_enorm);
    cudaGetSymbolAddress((void**)&dis, g_dis);

    cudaFuncSetAttribute(gemm_bf16x3<true>,
                         cudaFuncAttributeMaxDynamicSharedMemorySize, GEMM_SMEM_BYTES);
    cudaFuncSetAttribute(gemm_bf16x3<false>,
                         cudaFuncAttributeMaxDynamicSharedMemorySize, GEMM_SMEM_BYTES);

    const int* e_row = ei;
    const int* e_col = ei + E;

    // ---- CSR build ----
    cudaMemsetAsync(cnt, 0, N * sizeof(int));
    hist_kernel<<<(E + 255) / 256, 256>>>(e_col, cnt, E);
    dis_kernel<<<(N + 255) / 256, 256>>>(cnt, dis, N);
    scan_kernel<<<1, 1024>>>(cnt, ptr, cursor, N);
    scatter_kernel<<<(E + 255) / 256, 256>>>(e_row, e_col, dis, cursor, srcIdx, enorm, E);

    // ---- folded scale/shift (all layers, one launch) ----
    ss_all_kernel<<<3, H3>>>(conv1_b, bn1_g, bn1_b, bn1_m, bn1_v,
                             conv2_b, bn2_g, bn2_b, bn2_m, bn2_v,
                             conv3_b, bn3_g, bn3_b, bn3_m, bn3_v, sc, sh);

    dim3 gemmGrid3((N + 127) / 128, 3);
    dim3 gemmGrid1((N + 127) / 128, 1);
    const int h1Blocks = (N + 7) / 8;
    const int h2Blocks = (N + 15) / 16;

    // ---- layer 1: project first (K=128), then aggregate narrow ----
    gemm_bf16x3<true><<<gemmGrid3, 256, GEMM_SMEM_BYTES>>>(x, conv1_W, nullptr, sc, sh,
                                                           Ha, Zr, nullptr, N, DD, HH);
    spmm_h1<<<h1Blocks, 256>>>((const float4*)Zr, (float4*)Ha, (float4*)Zs,
                               ptr, srcIdx, enorm, dis, sc + 60, sh + 60, N);
    spmm_h2<<<h2Blocks, 256>>>((const float4*)Zs, (float4*)Ha,
                               ptr, srcIdx, enorm, dis, sc + 120, sh + 120, N);

    // ---- layer 2 (K=180) ----
    gemm_bf16x3<true><<<gemmGrid3, 256, GEMM_SMEM_BYTES>>>(Ha, conv2_W, nullptr, sc + H3, sh + H3,
                                                           Hb, Zr, nullptr, N, H3, HH);
    spmm_h1<<<h1Blocks, 256>>>((const float4*)Zr, (float4*)Hb, (float4*)Zs,
                               ptr, srcIdx, enorm, dis, sc + H3 + 60, sh + H3 + 60, N);
    spmm_h2<<<h2Blocks, 256>>>((const float4*)Zs, (float4*)Hb,
                               ptr, srcIdx, enorm, dis, sc + H3 + 120, sh + H3 + 120, N);

    // ---- layer 3 (K=180) ----
    gemm_bf16x3<true><<<gemmGrid3, 256, GEMM_SMEM_BYTES>>>(Hb, conv3_W, nullptr,
                                                           sc + 2 * H3, sh + 2 * H3,
                                                           Ha, Zr, nullptr, N, H3, HH);
    spmm_h1<<<h1Blocks, 256>>>((const float4*)Zr, (float4*)Ha, (float4*)Zs,
                               ptr, srcIdx, enorm, dis, sc + 2 * H3 + 60, sh + 2 * H3 + 60, N);
    spmm_h2<<<h2Blocks, 256>>>((const float4*)Zs, (float4*)Ha,
                               ptr, srcIdx, enorm, dis, sc + 2 * H3 + 120, sh + 2 * H3 + 120, N);

    // ---- final linear ----
    gemm_bf16x3<false><<<gemmGrid1, 256, GEMM_SMEM_BYTES>>>(Ha, lin_W, lin_b, nullptr, nullptr,
                                                            nullptr, nullptr, out, N, H3, CC);
}

// round 8
// speedup vs baseline: 2.3132x; 1.0452x over previous
#include <cuda_runtime.h>
#include <cuda_bf16.h>

// ---------------- problem constants ----------------
#define NN 50000
#define EE 400000
#define DD 128
#define HH 60
#define H3 180
#define CC 40
#define BN_EPS 1e-5f

// ---------------- static scratch ----------------
__device__ float g_Zr[NN * 120];   // raw p=1,2 projections
__device__ float g_Zs[NN * 60];    // raw hop-1 result for p=2
__device__ float g_Ha[NN * H3];
__device__ float g_Hb[NN * H3];
__device__ float g_scale[3 * H3];
__device__ float g_shift[3 * H3];
__device__ int   g_cnt[NN];
__device__ int   g_ptr[NN + 1];
__device__ int   g_cursor[NN];
__device__ int   g_blockSum[256];
__device__ int   g_blockOff[256];
__device__ int   g_srcIdx[EE];
__device__ float g_enorm[EE];
__device__ float g_dis[NN];

// ---------------- CSR build ----------------
__global__ void hist_kernel(const int* __restrict__ col, int* __restrict__ cnt, int E) {
    int e = blockIdx.x * blockDim.x + threadIdx.x;
    if (e < E) atomicAdd(&cnt[col[e]], 1);
}

// per-256-block sums of cnt
__global__ void partial_kernel(const int* __restrict__ cnt, int* __restrict__ blockSum, int n) {
    __shared__ int ws[8];
    int i = blockIdx.x * 256 + threadIdx.x;
    int lane = threadIdx.x & 31, wid = threadIdx.x >> 5;
    int v = (i < n) ? cnt[i] : 0;
    #pragma unroll
    for (int off = 16; off > 0; off >>= 1) v += __shfl_down_sync(0xffffffffu, v, off);
    if (lane == 0) ws[wid] = v;
    __syncthreads();
    if (wid == 0) {
        int s = (lane < 8) ? ws[lane] : 0;
        #pragma unroll
        for (int off = 4; off > 0; off >>= 1) s += __shfl_down_sync(0xffffffffu, s, off);
        if (lane == 0) blockSum[blockIdx.x] = s;
    }
}

// exclusive scan of <=256 block sums, single block
__global__ void scanblk_kernel(const int* __restrict__ blockSum, int* __restrict__ blockOff,
                               int nBlocks) {
    __shared__ int ws[8];
    int lane = threadIdx.x & 31, wid = threadIdx.x >> 5;
    int v = (threadIdx.x < nBlocks) ? blockSum[threadIdx.x] : 0;
    int x = v;
    #pragma unroll
    for (int off = 1; off < 32; off <<= 1) {
        int t = __shfl_up_sync(0xffffffffu, x, off);
        if (lane >= off) x += t;
    }
    if (lane == 31) ws[wid] = x;
    __syncthreads();
    if (wid == 0 && lane < 8) {
        int w = ws[lane];
        #pragma unroll
        for (int off = 1; off < 8; off <<= 1) {
            int t = __shfl_up_sync(0xffu, w, off);
            if (lane >= off) w += t;
        }
        ws[lane] = w;
    }
    __syncthreads();
    int woff = wid ? ws[wid - 1] : 0;
    if (threadIdx.x < nBlocks) blockOff[threadIdx.x] = woff + x - v;
}

// re-scan each 256-chunk, add block offset, write ptr/cursor/dis
__global__ void scanwrite_kernel(const int* __restrict__ cnt, const int* __restrict__ blockOff,
                                 int* __restrict__ ptr, int* __restrict__ cursor,
                                 float* __restrict__ dis, int n) {
    __shared__ int ws[8];
    int i = blockIdx.x * 256 + threadIdx.x;
    int lane = threadIdx.x & 31, wid = threadIdx.x >> 5;
    int v = (i < n) ? cnt[i] : 0;
    int x = v;
    #pragma unroll
    for (int off = 1; off < 32; off <<= 1) {
        int t = __shfl_up_sync(0xffffffffu, x, off);
        if (lane >= off) x += t;
    }
    if (lane == 31) ws[wid] = x;
    __syncthreads();
    if (wid == 0 && lane < 8) {
        int w = ws[lane];
        #pragma unroll
        for (int off = 1; off < 8; off <<= 1) {
            int t = __shfl_up_sync(0xffu, w, off);
            if (lane >= off) w += t;
        }
        ws[lane] = w;
    }
    __syncthreads();
    int woff = wid ? ws[wid - 1] : 0;
    int excl = blockOff[blockIdx.x] + woff + x - v;
    if (i < n) {
        ptr[i] = excl;
        cursor[i] = excl;
        dis[i] = rsqrtf((float)(v + 1));   // +1 self loop
        if (i == n - 1) ptr[n] = excl + v;
    }
}

__global__ void scatter_kernel(const int* __restrict__ row, const int* __restrict__ col,
                               const float* __restrict__ dis, int* __restrict__ cursor,
                               int* __restrict__ srcIdx, float* __restrict__ enorm, int E) {
    int e = blockIdx.x * blockDim.x + threadIdx.x;
    if (e < E) {
        int r = row[e], c = col[e];
        int pos = atomicAdd(&cursor[c], 1);
        srcIdx[pos] = r;
        enorm[pos]  = dis[r] * dis[c];
    }
}

// ---------------- folded BN scale/shift precompute ----------------
__global__ void ss_all_kernel(const float* __restrict__ b1c, const float* __restrict__ g1,
                              const float* __restrict__ b1, const float* __restrict__ m1,
                              const float* __restrict__ v1,
                              const float* __restrict__ b2c, const float* __restrict__ g2,
                              const float* __restrict__ b2, const float* __restrict__ m2,
                              const float* __restrict__ v2,
                              const float* __restrict__ b3c, const float* __restrict__ g3,
                              const float* __restrict__ b3, const float* __restrict__ m3,
                              const float* __restrict__ v3,
                              float* __restrict__ sc, float* __restrict__ sh) {
    int L = blockIdx.x;
    int c = threadIdx.x;
    if (c >= H3) return;
    const float* cb = (L == 0) ? b1c : (L == 1) ? b2c : b3c;
    const float* g  = (L == 0) ? g1  : (L == 1) ? g2  : g3;
    const float* b  = (L == 0) ? b1  : (L == 1) ? b2  : b3;
    const float* m  = (L == 0) ? m1  : (L == 1) ? m2  : m3;
    const float* v  = (L == 0) ? v1  : (L == 1) ? v2  : v3;
    float s = g[c] * rsqrtf(v[c] + BN_EPS);
    sc[L * H3 + c] = s;
    sh[L * H3 + c] = (cb[c] - m[c]) * s + b[c];
}

// ---------------- SpMM hop 1: 120-wide ----------------
__global__ void __launch_bounds__(256)
spmm_h1(const float4* __restrict__ Zr, float4* __restrict__ H, float4* __restrict__ Zs,
        const int* __restrict__ ptr, const int* __restrict__ srcIdx,
        const float* __restrict__ enorm, const float* __restrict__ dis,
        const float* __restrict__ ssS, const float* __restrict__ ssH, int N) {
    const int lane = threadIdx.x & 31;
    const int node = blockIdx.x * 8 + (threadIdx.x >> 5);
    if (node >= N) return;
    const bool act = lane < 30;

    float d = dis[node];
    float dd = d * d;
    float4 acc = make_float4(0.f, 0.f, 0.f, 0.f);
    if (act) {
        float4 v = Zr[node * 30 + lane];
        acc.x = dd * v.x; acc.y = dd * v.y; acc.z = dd * v.z; acc.w = dd * v.w;
    }

    int s = ptr[node], e = ptr[node + 1];
    int k = s;
    for (; k + 1 < e; k += 2) {
        int s0 = srcIdx[k], s1 = srcIdx[k + 1];
        float w0 = enorm[k], w1 = enorm[k + 1];
        if (act) {
            float4 v0 = Zr[s0 * 30 + lane];
            float4 v1 = Zr[s1 * 30 + lane];
            acc.x += w0 * v0.x; acc.y += w0 * v0.y; acc.z += w0 * v0.z; acc.w += w0 * v0.w;
            acc.x += w1 * v1.x; acc.y += w1 * v1.y; acc.z += w1 * v1.z; acc.w += w1 * v1.w;
        }
    }
    if (k < e) {
        int s0 = srcIdx[k];
        float w0 = enorm[k];
        if (act) {
            float4 v0 = Zr[s0 * 30 + lane];
            acc.x += w0 * v0.x; acc.y += w0 * v0.y; acc.z += w0 * v0.z; acc.w += w0 * v0.w;
        }
    }

    if (lane < 15) {
        float4 sc = reinterpret_cast<const float4*>(ssS)[lane];
        float4 sh = reinterpret_cast<const float4*>(ssH)[lane];
        float4 o;
        o.x = acc.x * sc.x + sh.x;
        o.y = acc.y * sc.y + sh.y;
        o.z = acc.z * sc.z + sh.z;
        o.w = acc.w * sc.w + sh.w;
        H[node * 45 + 15 + lane] = o;       // H[:, 60:120]
    } else if (act) {
        Zs[node * 15 + (lane - 15)] = acc;  // raw p=2 hop-1
    }
}

// ---------------- SpMM hop 2: 60-wide ----------------
__global__ void __launch_bounds__(256)
spmm_h2(const float4* __restrict__ Zs, float4* __restrict__ H,
        const int* __restrict__ ptr, const int* __restrict__ srcIdx,
        const float* __restrict__ enorm, const float* __restrict__ dis,
        const float* __restrict__ ssS, const float* __restrict__ ssH, int N) {
    const int l = threadIdx.x & 15;
    const int node = blockIdx.x * 16 + (threadIdx.x >> 4);
    if (node >= N) return;
    const bool act = l < 15;

    float d = dis[node];
    float dd = d * d;
    float4 acc = make_float4(0.f, 0.f, 0.f, 0.f);
    if (act) {
        float4 v = Zs[node * 15 + l];
        acc.x = dd * v.x; acc.y = dd * v.y; acc.z = dd * v.z; acc.w = dd * v.w;
    }

    int s = ptr[node], e = ptr[node + 1];
    int k = s;
    for (; k + 1 < e; k += 2) {
        int s0 = srcIdx[k], s1 = srcIdx[k + 1];
        float w0 = enorm[k], w1 = enorm[k + 1];
        if (act) {
            float4 v0 = Zs[s0 * 15 + l];
            float4 v1 = Zs[s1 * 15 + l];
            acc.x += w0 * v0.x; acc.y += w0 * v0.y; acc.z += w0 * v0.z; acc.w += w0 * v0.w;
            acc.x += w1 * v1.x; acc.y += w1 * v1.y; acc.z += w1 * v1.z; acc.w += w1 * v1.w;
        }
    }
    if (k < e) {
        int s0 = srcIdx[k];
        float w0 = enorm[k];
        if (act) {
            float4 v0 = Zs[s0 * 15 + l];
            acc.x += w0 * v0.x; acc.y += w0 * v0.y; acc.z += w0 * v0.z; acc.w += w0 * v0.w;
        }
    }

    if (act) {
        float4 sc = reinterpret_cast<const float4*>(ssS)[l];
        float4 sh = reinterpret_cast<const float4*>(ssH)[l];
        float4 o;
        o.x = acc.x * sc.x + sh.x;
        o.y = acc.y * sc.y + sh.y;
        o.z = acc.z * sc.z + sh.z;
        o.w = acc.w * sc.w + sh.w;
        H[node * 45 + 30 + l] = o;          // H[:, 120:180]
    }
}

// ---------------- bf16 split helpers ----------------
__device__ __forceinline__ unsigned pk_bf2(float x, float y) {
    __nv_bfloat162 p = __floats2bfloat162_rn(x, y);
    return *reinterpret_cast<unsigned*>(&p);
}

__device__ __forceinline__ void mma_bf16(float* d, unsigned a0, unsigned a1,
                                         unsigned a2, unsigned a3,
                                         unsigned b0, unsigned b1) {
    asm volatile("mma.sync.aligned.m16n8k16.row.col.f32.bf16.bf16.f32 "
                 "{%0,%1,%2,%3}, {%4,%5,%6,%7}, {%8,%9}, {%0,%1,%2,%3};"
                 : "+f"(d[0]), "+f"(d[1]), "+f"(d[2]), "+f"(d[3])
                 : "r"(a0), "r"(a1), "r"(a2), "r"(a3), "r"(b0), "r"(b1));
}

template <int ITERS, int THREADS>
__device__ __forceinline__ void ldg_tile(const float* __restrict__ base, int row0,
                                         int rows_max, int K, int kb, int tid,
                                         float2 v[ITERS]) {
    #pragma unroll
    for (int it = 0; it < ITERS; it++) {
        int idx = tid + it * THREADS;
        int r = idx >> 4, j = idx & 15;
        int gr = row0 + r, gk = kb + 2 * j;
        v[it] = (gr < rows_max && gk < K)
                ? *reinterpret_cast<const float2*>(&base[(size_t)gr * K + gk])
                : make_float2(0.f, 0.f);
    }
}

template <int ITERS, int THREADS>
__device__ __forceinline__ void sts_tile(unsigned* buf, int tid, const float2 v[ITERS]) {
    #pragma unroll
    for (int it = 0; it < ITERS; it++) {
        int idx = tid + it * THREADS;
        int r = idx >> 4, j = idx & 15;
        float2 a = v[it];
        __nv_bfloat16 hx = __float2bfloat16_rn(a.x);
        __nv_bfloat16 hy = __float2bfloat16_rn(a.y);
        float mx = a.x - __bfloat162float(hx);
        float my = a.y - __bfloat162float(hy);
        __nv_bfloat162 hp; hp.x = hx; hp.y = hy;
        unsigned hi = *reinterpret_cast<unsigned*>(&hp);
        unsigned mid = pk_bf2(mx, my);
        *reinterpret_cast<uint2*>(&buf[r * 36 + 2 * j]) = make_uint2(hi, mid);
    }
}

// ---------------- fused conv GEMM: A[Nx K] @ Wall[180 x K]^T, 128x192 tile ----
// cols 0:60 -> finalized (scale/shift) into Hdst[:,0:60]; cols 60:180 -> raw Zr.
#define FUSED_SMEM_BYTES ((2 * 128 * 36 + 2 * 192 * 36) * 4)

__global__ void __launch_bounds__(512, 1)
gemm_conv_fused(const float* __restrict__ A, const float* __restrict__ Wall,
                const float* __restrict__ ssS, const float* __restrict__ ssH,
                float* __restrict__ Hdst, float* __restrict__ Zr, int N, int K) {
    extern __shared__ unsigned smem_u[];
    unsigned* sA = smem_u;                    // [2][128][36]
    unsigned* sW = smem_u + 2 * 128 * 36;     // [2][192][36]

    const int tid  = threadIdx.x;
    const int lane = tid & 31;
    const int wid  = tid >> 5;
    const int warpM = wid & 3;    // 4 x 32 rows
    const int warpN = wid >> 2;   // 4 x 48 cols
    const int row0 = blockIdx.x * 128;
    const int g = lane >> 2;
    const int t = lane & 3;
    const int mBase = warpM * 32;

    float acc[2][6][4];
    #pragma unroll
    for (int mt = 0; mt < 2; mt++)
        #pragma unroll
        for (int nt = 0; nt < 6; nt++)
            #pragma unroll
            for (int j = 0; j < 4; j++) acc[mt][nt][j] = 0.0f;

    float2 aReg[4], wReg[6];
    ldg_tile<4, 512>(A, row0, N, K, 0, tid, aReg);
    ldg_tile<6, 512>(Wall, 0, H3, K, 0, tid, wReg);
    sts_tile<4, 512>(sA, tid, aReg);
    sts_tile<6, 512>(sW, tid, wReg);
    __syncthreads();

    const int nC = (K + 31) / 32;
    for (int c = 0; c < nC; c++) {
        const int cur = c & 1;
        const unsigned* cA = sA + cur * 128 * 36;
        const unsigned* cW = sW + cur * 192 * 36;
        if (c + 1 < nC) {
            ldg_tile<4, 512>(A, row0, N, K, (c + 1) * 32, tid, aReg);
            ldg_tile<6, 512>(Wall, 0, H3, K, (c + 1) * 32, tid, wReg);
        }
        #pragma unroll
        for (int ks = 0; ks < 2; ks++) {
            const int pb = 2 * (8 * ks + t);
            uint2 aF[2][4];
            #pragma unroll
            for (int mt = 0; mt < 2; mt++) {
                const int br = mBase + mt * 16 + g;
                aF[mt][0] = *reinterpret_cast<const uint2*>(&cA[br * 36 + pb]);
                aF[mt][1] = *reinterpret_cast<const uint2*>(&cA[(br + 8) * 36 + pb]);
                aF[mt][2] = *reinterpret_cast<const uint2*>(&cA[br * 36 + pb + 8]);
                aF[mt][3] = *reinterpret_cast<const uint2*>(&cA[(br + 8) * 36 + pb + 8]);
            }
            #pragma unroll
            for (int nt = 0; nt < 6; nt++) {
                const int bn_ = warpN * 48 + nt * 8 + g;
                uint2 b0 = *reinterpret_cast<const uint2*>(&cW[bn_ * 36 + pb]);
                uint2 b1 = *reinterpret_cast<const uint2*>(&cW[bn_ * 36 + pb + 8]);
                #pragma unroll
                for (int mt = 0; mt < 2; mt++) {
                    mma_bf16(acc[mt][nt], aF[mt][0].x, aF[mt][1].x, aF[mt][2].x, aF[mt][3].x, b0.x, b1.x); // hi*hi
                    mma_bf16(acc[mt][nt], aF[mt][0].x, aF[mt][1].x, aF[mt][2].x, aF[mt][3].x, b0.y, b1.y); // hi*mid
                    mma_bf16(acc[mt][nt], aF[mt][0].y, aF[mt][1].y, aF[mt][2].y, aF[mt][3].y, b0.x, b1.x); // mid*hi
                }
            }
        }
        if (c + 1 < nC) {
            sts_tile<4, 512>(sA + ((c + 1) & 1) * 128 * 36, tid, aReg);
            sts_tile<6, 512>(sW + ((c + 1) & 1) * 192 * 36, tid, wReg);
        }
        __syncthreads();
    }

    #pragma unroll
    for (int mt = 0; mt < 2; mt++) {
        const int rlo = row0 + mBase + mt * 16 + g;
        #pragma unroll
        for (int nt = 0; nt < 6; nt++) {
            const int cb = warpN * 48 + nt * 8 + 2 * t;
            #pragma unroll
            for (int jj = 0; jj < 2; jj++) {
                int c = cb + jj;
                if (c >= H3) continue;
                float v0 = acc[mt][nt][jj];
                float v1 = acc[mt][nt][2 + jj];
                if (c < 60) {
                    float sc = ssS[c], sh = ssH[c];
                    if (rlo < N)     Hdst[(size_t)rlo * H3 + c] = v0 * sc + sh;
                    if (rlo + 8 < N) Hdst[(size_t)(rlo + 8) * H3 + c] = v1 * sc + sh;
                } else {
                    int zc = c - 60;
                    if (rlo < N)     Zr[(size_t)rlo * 120 + zc] = v0;
                    if (rlo + 8 < N) Zr[(size_t)(rlo + 8) * 120 + zc] = v1;
                }
            }
        }
    }
}

// ---------------- final linear GEMM (128x64 tile, bias only) ----------------
#define GEMM_SMEM_BYTES ((2 * 128 * 36 + 2 * 64 * 36) * 4)

__global__ void __launch_bounds__(256, 2)
gemm_final(const float* __restrict__ A, const float* __restrict__ W,
           const float* __restrict__ bias, float* __restrict__ outF, int N, int K, int Cc) {
    extern __shared__ unsigned smem_u[];
    unsigned* sA = smem_u;                    // [2][128][36]
    unsigned* sW = smem_u + 2 * 128 * 36;     // [2][64][36]

    const int tid  = threadIdx.x;
    const int lane = tid & 31;
    const int wid  = tid >> 5;
    const int warpM = wid & 3;
    const int warpN = wid >> 2;
    const int row0 = blockIdx.x * 128;
    const int g = lane >> 2;
    const int t = lane & 3;
    const int mBase = warpM * 32;

    float acc[2][4][4];
    #pragma unroll
    for (int mt = 0; mt < 2; mt++)
        #pragma unroll
        for (int nt = 0; nt < 4; nt++)
            #pragma unroll
            for (int j = 0; j < 4; j++) acc[mt][nt][j] = 0.0f;

    float2 aReg[8], wReg[4];
    ldg_tile<8, 256>(A, row0, N, K, 0, tid, aReg);
    ldg_tile<4, 256>(W, 0, Cc, K, 0, tid, wReg);
    sts_tile<8, 256>(sA, tid, aReg);
    sts_tile<4, 256>(sW, tid, wReg);
    __syncthreads();

    const int nC = (K + 31) / 32;
    for (int c = 0; c < nC; c++) {
        const int cur = c & 1;
        const unsigned* cA = sA + cur * 128 * 36;
        const unsigned* cW = sW + cur * 64 * 36;
        if (c + 1 < nC) {
            ldg_tile<8, 256>(A, row0, N, K, (c + 1) * 32, tid, aReg);
            ldg_tile<4, 256>(W, 0, Cc, K, (c + 1) * 32, tid, wReg);
        }
        #pragma unroll
        for (int ks = 0; ks < 2; ks++) {
            const int pb = 2 * (8 * ks + t);
            uint2 aF[2][4];
            #pragma unroll
            for (int mt = 0; mt < 2; mt++) {
                const int br = mBase + mt * 16 + g;
                aF[mt][0] = *reinterpret_cast<const uint2*>(&cA[br * 36 + pb]);
                aF[mt][1] = *reinterpret_cast<const uint2*>(&cA[(br + 8) * 36 + pb]);
                aF[mt][2] = *reinterpret_cast<const uint2*>(&cA[br * 36 + pb + 8]);
                aF[mt][3] = *reinterpret_cast<const uint2*>(&cA[(br + 8) * 36 + pb + 8]);
            }
            #pragma unroll
            for (int nt = 0; nt < 4; nt++) {
                const int bn_ = warpN * 32 + nt * 8 + g;
                uint2 b0 = *reinterpret_cast<const uint2*>(&cW[bn_ * 36 + pb]);
                uint2 b1 = *reinterpret_cast<const uint2*>(&cW[bn_ * 36 + pb + 8]);
                #pragma unroll
                for (int mt = 0; mt < 2; mt++) {
                    mma_bf16(acc[mt][nt], aF[mt][0].x, aF[mt][1].x, aF[mt][2].x, aF[mt][3].x, b0.x, b1.x);
                    mma_bf16(acc[mt][nt], aF[mt][0].x, aF[mt][1].x, aF[mt][2].x, aF[mt][3].x, b0.y, b1.y);
                    mma_bf16(acc[mt][nt], aF[mt][0].y, aF[mt][1].y, aF[mt][2].y, aF[mt][3].y, b0.x, b1.x);
                }
            }
        }
        if (c + 1 < nC) {
            sts_tile<8, 256>(sA + ((c + 1) & 1) * 128 * 36, tid, aReg);
            sts_tile<4, 256>(sW + ((c + 1) & 1) * 64 * 36, tid, wReg);
        }
        __syncthreads();
    }

    #pragma unroll
    for (int mt = 0; mt < 2; mt++) {
        const int rlo = row0 + mBase + mt * 16 + g;
        #pragma unroll
        for (int nt = 0; nt < 4; nt++) {
            const int cb = warpN * 32 + nt * 8 + 2 * t;
            #pragma unroll
            for (int jj = 0; jj < 2; jj++) {
                int c = cb + jj;
                if (c >= Cc) continue;
                float add = bias[c];
                if (rlo < N)     outF[(size_t)rlo * CC + c] = acc[mt][nt][jj] + add;
                if (rlo + 8 < N) outF[(size_t)(rlo + 8) * CC + c] = acc[mt][nt][2 + jj] + add;
            }
        }
    }
}

// ---------------- host launch ----------------
extern "C" void kernel_launch(void* const* d_in, const int* in_sizes, int n_in,
                              void* d_out, int out_size) {
    const float* x       = (const float*)d_in[0];
    const int*   ei      = (const int*)d_in[1];
    const float* conv1_W = (const float*)d_in[2];
    const float* conv1_b = (const float*)d_in[3];
    const float* conv2_W = (const float*)d_in[4];
    const float* conv2_b = (const float*)d_in[5];
    const float* conv3_W = (const float*)d_in[6];
    const float* conv3_b = (const float*)d_in[7];
    const float* bn1_g = (const float*)d_in[8];
    const float* bn1_b = (const float*)d_in[9];
    const float* bn1_m = (const float*)d_in[10];
    const float* bn1_v = (const float*)d_in[11];
    const float* bn2_g = (const float*)d_in[12];
    const float* bn2_b = (const float*)d_in[13];
    const float* bn2_m = (const float*)d_in[14];
    const float* bn2_v = (const float*)d_in[15];
    const float* bn3_g = (const float*)d_in[16];
    const float* bn3_b = (const float*)d_in[17];
    const float* bn3_m = (const float*)d_in[18];
    const float* bn3_v = (const float*)d_in[19];
    const float* lin_W = (const float*)d_in[20];
    const float* lin_b = (const float*)d_in[21];
    float* out = (float*)d_out;

    const int N = in_sizes[0] / DD;
    const int E = in_sizes[1] / 2;

    float *Zr, *Zs, *Ha, *Hb, *enorm, *dis, *sc, *sh;
    int *cnt, *ptr, *cursor, *srcIdx, *blockSum, *blockOff;
    cudaGetSymbolAddress((void**)&Zr, g_Zr);
    cudaGetSymbolAddress((void**)&Zs, g_Zs);
    cudaGetSymbolAddress((void**)&Ha, g_Ha);
    cudaGetSymbolAddress((void**)&Hb, g_Hb);
    cudaGetSymbolAddress((void**)&sc, g_scale);
    cudaGetSymbolAddress((void**)&sh, g_shift);
    cudaGetSymbolAddress((void**)&cnt, g_cnt);
    cudaGetSymbolAddress((void**)&ptr, g_ptr);
    cudaGetSymbolAddress((void**)&cursor, g_cursor);
    cudaGetSymbolAddress((void**)&srcIdx, g_srcIdx);
    cudaGetSymbolAddress((void**)&enorm, g_enorm);
    cudaGetSymbolAddress((void**)&dis, g_dis);
    cudaGetSymbolAddress((void**)&blockSum, g_blockSum);
    cudaGetSymbolAddress((void**)&blockOff, g_blockOff);

    cudaFuncSetAttribute(gemm_conv_fused,
                         cudaFuncAttributeMaxDynamicSharedMemorySize, FUSED_SMEM_BYTES);
    cudaFuncSetAttribute(gemm_final,
                         cudaFuncAttributeMaxDynamicSharedMemorySize, GEMM_SMEM_BYTES);

    const int* e_row = ei;
    const int* e_col = ei + E;
    const int nScanBlocks = (N + 255) / 256;

    // ---- CSR build (parallel scan) ----
    cudaMemsetAsync(cnt, 0, N * sizeof(int));
    hist_kernel<<<(E + 255) / 256, 256>>>(e_col, cnt, E);
    partial_kernel<<<nScanBlocks, 256>>>(cnt, blockSum, N);
    scanblk_kernel<<<1, 256>>>(blockSum, blockOff, nScanBlocks);
    scanwrite_kernel<<<nScanBlocks, 256>>>(cnt, blockOff, ptr, cursor, dis, N);
    scatter_kernel<<<(E + 255) / 256, 256>>>(e_row, e_col, dis, cursor, srcIdx, enorm, E);

    // ---- folded scale/shift ----
    ss_all_kernel<<<3, H3>>>(conv1_b, bn1_g, bn1_b, bn1_m, bn1_v,
                             conv2_b, bn2_g, bn2_b, bn2_m, bn2_v,
                             conv3_b, bn3_g, bn3_b, bn3_m, bn3_v, sc, sh);

    const int gemmBlocks = (N + 127) / 128;
    const int h1Blocks = (N + 7) / 8;
    const int h2Blocks = (N + 15) / 16;

    // ---- layer 1 (K=128) ----
    gemm_conv_fused<<<gemmBlocks, 512, FUSED_SMEM_BYTES>>>(x, conv1_W, sc, sh, Ha, Zr, N, DD);
    spmm_h1<<<h1Blocks, 256>>>((const float4*)Zr, (float4*)Ha, (float4*)Zs,
                               ptr, srcIdx, enorm, dis, sc + 60, sh + 60, N);
    spmm_h2<<<h2Blocks, 256>>>((const float4*)Zs, (float4*)Ha,
                               ptr, srcIdx, enorm, dis, sc + 120, sh + 120, N);

    // ---- layer 2 (K=180) ----
    gemm_conv_fused<<<gemmBlocks, 512, FUSED_SMEM_BYTES>>>(Ha, conv2_W, sc + H3, sh + H3,
                                                           Hb, Zr, N, H3);
    spmm_h1<<<h1Blocks, 256>>>((const float4*)Zr, (float4*)Hb, (float4*)Zs,
                               ptr, srcIdx, enorm, dis, sc + H3 + 60, sh + H3 + 60, N);
    spmm_h2<<<h2Blocks, 256>>>((const float4*)Zs, (float4*)Hb,
                               ptr, srcIdx, enorm, dis, sc + H3 + 120, sh + H3 + 120, N);

    // ---- layer 3 (K=180) ----
    gemm_conv_fused<<<gemmBlocks, 512, FUSED_SMEM_BYTES>>>(Hb, conv3_W,
                                                           sc + 2 * H3, sh + 2 * H3,
                                                           Ha, Zr, N, H3);
    spmm_h1<<<h1Blocks, 256>>>((const float4*)Zr, (float4*)Ha, (float4*)Zs,
                               ptr, srcIdx, enorm, dis, sc + 2 * H3 + 60, sh + 2 * H3 + 60, N);
    spmm_h2<<<h2Blocks, 256>>>((const float4*)Zs, (float4*)Ha,
                               ptr, srcIdx, enorm, dis, sc + 2 * H3 + 120, sh + 2 * H3 + 120, N);

    // ---- final linear ----
    gemm_final<<<gemmBlocks, 256, GEMM_SMEM_BYTES>>>(Ha, lin_W, lin_b, out, N, H3, CC);
}

// round 9
// speedup vs baseline: 2.4664x; 1.0662x over previous
#include <cuda_runtime.h>
#include <cuda_bf16.h>

// ---------------- problem constants ----------------
#define NN 50000
#define EE 400000
#define DD 128
#define HH 60
#define H3 180
#define CC 40
#define BN_EPS 1e-5f

// ---------------- static scratch ----------------
__device__ float g_Zr[NN * 120];   // raw p=1,2 projections
__device__ float g_Zs[NN * 60];    // raw hop-1 result for p=2
__device__ float g_Ha[NN * H3];
__device__ float g_Hb[NN * H3];
__device__ float g_scale[3 * H3];
__device__ float g_shift[3 * H3];
__device__ int   g_cnt[NN];
__device__ int   g_ptr[NN + 1];
__device__ int   g_cursor[NN];
__device__ int   g_blockSum[256];
__device__ int   g_blockOff[256];
__device__ int   g_srcIdx[EE];
__device__ float g_enorm[EE];
__device__ float g_dis[NN];

// ---------------- CSR build ----------------
__global__ void hist_kernel(const int* __restrict__ col, int* __restrict__ cnt, int E) {
    int e = blockIdx.x * blockDim.x + threadIdx.x;
    if (e < E) atomicAdd(&cnt[col[e]], 1);
}

// per-256-block sums of cnt
__global__ void partial_kernel(const int* __restrict__ cnt, int* __restrict__ blockSum, int n) {
    __shared__ int ws[8];
    int i = blockIdx.x * 256 + threadIdx.x;
    int lane = threadIdx.x & 31, wid = threadIdx.x >> 5;
    int v = (i < n) ? cnt[i] : 0;
    #pragma unroll
    for (int off = 16; off > 0; off >>= 1) v += __shfl_down_sync(0xffffffffu, v, off);
    if (lane == 0) ws[wid] = v;
    __syncthreads();
    if (wid == 0) {
        int s = (lane < 8) ? ws[lane] : 0;
        #pragma unroll
        for (int off = 4; off > 0; off >>= 1) s += __shfl_down_sync(0xffffffffu, s, off);
        if (lane == 0) blockSum[blockIdx.x] = s;
    }
}

// exclusive scan of <=256 block sums, single block
__global__ void scanblk_kernel(const int* __restrict__ blockSum, int* __restrict__ blockOff,
                               int nBlocks) {
    __shared__ int ws[8];
    int lane = threadIdx.x & 31, wid = threadIdx.x >> 5;
    int v = (threadIdx.x < nBlocks) ? blockSum[threadIdx.x] : 0;
    int x = v;
    #pragma unroll
    for (int off = 1; off < 32; off <<= 1) {
        int t = __shfl_up_sync(0xffffffffu, x, off);
        if (lane >= off) x += t;
    }
    if (lane == 31) ws[wid] = x;
    __syncthreads();
    if (wid == 0 && lane < 8) {
        int w = ws[lane];
        #pragma unroll
        for (int off = 1; off < 8; off <<= 1) {
            int t = __shfl_up_sync(0xffu, w, off);
            if (lane >= off) w += t;
        }
        ws[lane] = w;
    }
    __syncthreads();
    int woff = wid ? ws[wid - 1] : 0;
    if (threadIdx.x < nBlocks) blockOff[threadIdx.x] = woff + x - v;
}

// re-scan each 256-chunk, add block offset, write ptr/cursor/dis
__global__ void scanwrite_kernel(const int* __restrict__ cnt, const int* __restrict__ blockOff,
                                 int* __restrict__ ptr, int* __restrict__ cursor,
                                 float* __restrict__ dis, int n) {
    __shared__ int ws[8];
    int i = blockIdx.x * 256 + threadIdx.x;
    int lane = threadIdx.x & 31, wid = threadIdx.x >> 5;
    int v = (i < n) ? cnt[i] : 0;
    int x = v;
    #pragma unroll
    for (int off = 1; off < 32; off <<= 1) {
        int t = __shfl_up_sync(0xffffffffu, x, off);
        if (lane >= off) x += t;
    }
    if (lane == 31) ws[wid] = x;
    __syncthreads();
    if (wid == 0 && lane < 8) {
        int w = ws[lane];
        #pragma unroll
        for (int off = 1; off < 8; off <<= 1) {
            int t = __shfl_up_sync(0xffu, w, off);
            if (lane >= off) w += t;
        }
        ws[lane] = w;
    }
    __syncthreads();
    int woff = wid ? ws[wid - 1] : 0;
    int excl = blockOff[blockIdx.x] + woff + x - v;
    if (i < n) {
        ptr[i] = excl;
        cursor[i] = excl;
        dis[i] = rsqrtf((float)(v + 1));   // +1 self loop
        if (i == n - 1) ptr[n] = excl + v;
    }
}

__global__ void scatter_kernel(const int* __restrict__ row, const int* __restrict__ col,
                               const float* __restrict__ dis, int* __restrict__ cursor,
                               int* __restrict__ srcIdx, float* __restrict__ enorm, int E) {
    int e = blockIdx.x * blockDim.x + threadIdx.x;
    if (e < E) {
        int r = row[e], c = col[e];
        int pos = atomicAdd(&cursor[c], 1);
        srcIdx[pos] = r;
        enorm[pos]  = dis[r] * dis[c];
    }
}

// ---------------- folded BN scale/shift precompute ----------------
__global__ void ss_all_kernel(const float* __restrict__ b1c, const float* __restrict__ g1,
                              const float* __restrict__ b1, const float* __restrict__ m1,
                              const float* __restrict__ v1,
                              const float* __restrict__ b2c, const float* __restrict__ g2,
                              const float* __restrict__ b2, const float* __restrict__ m2,
                              const float* __restrict__ v2,
                              const float* __restrict__ b3c, const float* __restrict__ g3,
                              const float* __restrict__ b3, const float* __restrict__ m3,
                              const float* __restrict__ v3,
                              float* __restrict__ sc, float* __restrict__ sh) {
    int L = blockIdx.x;
    int c = threadIdx.x;
    if (c >= H3) return;
    const float* cb = (L == 0) ? b1c : (L == 1) ? b2c : b3c;
    const float* g  = (L == 0) ? g1  : (L == 1) ? g2  : g3;
    const float* b  = (L == 0) ? b1  : (L == 1) ? b2  : b3;
    const float* m  = (L == 0) ? m1  : (L == 1) ? m2  : m3;
    const float* v  = (L == 0) ? v1  : (L == 1) ? v2  : v3;
    float s = g[c] * rsqrtf(v[c] + BN_EPS);
    sc[L * H3 + c] = s;
    sh[L * H3 + c] = (cb[c] - m[c]) * s + b[c];
}

// ---------------- SpMM hop 1: 120-wide (4-edge unroll) ----------------
__global__ void __launch_bounds__(256)
spmm_h1(const float4* __restrict__ Zr, float4* __restrict__ H, float4* __restrict__ Zs,
        const int* __restrict__ ptr, const int* __restrict__ srcIdx,
        const float* __restrict__ enorm, const float* __restrict__ dis,
        const float* __restrict__ ssS, const float* __restrict__ ssH, int N) {
    const int lane = threadIdx.x & 31;
    const int node = blockIdx.x * 8 + (threadIdx.x >> 5);
    if (node >= N) return;
    const bool act = lane < 30;

    float d = dis[node];
    float dd = d * d;
    float4 acc = make_float4(0.f, 0.f, 0.f, 0.f);
    if (act) {
        float4 v = Zr[node * 30 + lane];
        acc.x = dd * v.x; acc.y = dd * v.y; acc.z = dd * v.z; acc.w = dd * v.w;
    }

    int s = ptr[node], e = ptr[node + 1];
    int k = s;
    for (; k + 3 < e; k += 4) {
        int s0 = srcIdx[k], s1 = srcIdx[k + 1], s2 = srcIdx[k + 2], s3 = srcIdx[k + 3];
        float w0 = enorm[k], w1 = enorm[k + 1], w2 = enorm[k + 2], w3 = enorm[k + 3];
        if (act) {
            float4 v0 = Zr[s0 * 30 + lane];
            float4 v1 = Zr[s1 * 30 + lane];
            float4 v2 = Zr[s2 * 30 + lane];
            float4 v3 = Zr[s3 * 30 + lane];
            acc.x += w0 * v0.x; acc.y += w0 * v0.y; acc.z += w0 * v0.z; acc.w += w0 * v0.w;
            acc.x += w1 * v1.x; acc.y += w1 * v1.y; acc.z += w1 * v1.z; acc.w += w1 * v1.w;
            acc.x += w2 * v2.x; acc.y += w2 * v2.y; acc.z += w2 * v2.z; acc.w += w2 * v2.w;
            acc.x += w3 * v3.x; acc.y += w3 * v3.y; acc.z += w3 * v3.z; acc.w += w3 * v3.w;
        }
    }
    for (; k < e; k++) {
        int s0 = srcIdx[k];
        float w0 = enorm[k];
        if (act) {
            float4 v0 = Zr[s0 * 30 + lane];
            acc.x += w0 * v0.x; acc.y += w0 * v0.y; acc.z += w0 * v0.z; acc.w += w0 * v0.w;
        }
    }

    if (lane < 15) {
        float4 sc = reinterpret_cast<const float4*>(ssS)[lane];
        float4 sh = reinterpret_cast<const float4*>(ssH)[lane];
        float4 o;
        o.x = acc.x * sc.x + sh.x;
        o.y = acc.y * sc.y + sh.y;
        o.z = acc.z * sc.z + sh.z;
        o.w = acc.w * sc.w + sh.w;
        H[node * 45 + 15 + lane] = o;       // H[:, 60:120]
    } else if (act) {
        Zs[node * 15 + (lane - 15)] = acc;  // raw p=2 hop-1
    }
}

// ---------------- SpMM hop 2: 60-wide (4-edge unroll) ----------------
__global__ void __launch_bounds__(256)
spmm_h2(const float4* __restrict__ Zs, float4* __restrict__ H,
        const int* __restrict__ ptr, const int* __restrict__ srcIdx,
        const float* __restrict__ enorm, const float* __restrict__ dis,
        const float* __restrict__ ssS, const float* __restrict__ ssH, int N) {
    const int l = threadIdx.x & 15;
    const int node = blockIdx.x * 16 + (threadIdx.x >> 4);
    if (node >= N) return;
    const bool act = l < 15;

    float d = dis[node];
    float dd = d * d;
    float4 acc = make_float4(0.f, 0.f, 0.f, 0.f);
    if (act) {
        float4 v = Zs[node * 15 + l];
        acc.x = dd * v.x; acc.y = dd * v.y; acc.z = dd * v.z; acc.w = dd * v.w;
    }

    int s = ptr[node], e = ptr[node + 1];
    int k = s;
    for (; k + 3 < e; k += 4) {
        int s0 = srcIdx[k], s1 = srcIdx[k + 1], s2 = srcIdx[k + 2], s3 = srcIdx[k + 3];
        float w0 = enorm[k], w1 = enorm[k + 1], w2 = enorm[k + 2], w3 = enorm[k + 3];
        if (act) {
            float4 v0 = Zs[s0 * 15 + l];
            float4 v1 = Zs[s1 * 15 + l];
            float4 v2 = Zs[s2 * 15 + l];
            float4 v3 = Zs[s3 * 15 + l];
            acc.x += w0 * v0.x; acc.y += w0 * v0.y; acc.z += w0 * v0.z; acc.w += w0 * v0.w;
            acc.x += w1 * v1.x; acc.y += w1 * v1.y; acc.z += w1 * v1.z; acc.w += w1 * v1.w;
            acc.x += w2 * v2.x; acc.y += w2 * v2.y; acc.z += w2 * v2.z; acc.w += w2 * v2.w;
            acc.x += w3 * v3.x; acc.y += w3 * v3.y; acc.z += w3 * v3.z; acc.w += w3 * v3.w;
        }
    }
    for (; k < e; k++) {
        int s0 = srcIdx[k];
        float w0 = enorm[k];
        if (act) {
            float4 v0 = Zs[s0 * 15 + l];
            acc.x += w0 * v0.x; acc.y += w0 * v0.y; acc.z += w0 * v0.z; acc.w += w0 * v0.w;
        }
    }

    if (act) {
        float4 sc = reinterpret_cast<const float4*>(ssS)[l];
        float4 sh = reinterpret_cast<const float4*>(ssH)[l];
        float4 o;
        o.x = acc.x * sc.x + sh.x;
        o.y = acc.y * sc.y + sh.y;
        o.z = acc.z * sc.z + sh.z;
        o.w = acc.w * sc.w + sh.w;
        H[node * 45 + 30 + l] = o;          // H[:, 120:180]
    }
}

// ---------------- bf16 split helpers ----------------
__device__ __forceinline__ unsigned pk_bf2(float x, float y) {
    __nv_bfloat162 p = __floats2bfloat162_rn(x, y);
    return *reinterpret_cast<unsigned*>(&p);
}

__device__ __forceinline__ void mma_bf16(float* d, unsigned a0, unsigned a1,
                                         unsigned a2, unsigned a3,
                                         unsigned b0, unsigned b1) {
    asm volatile("mma.sync.aligned.m16n8k16.row.col.f32.bf16.bf16.f32 "
                 "{%0,%1,%2,%3}, {%4,%5,%6,%7}, {%8,%9}, {%0,%1,%2,%3};"
                 : "+f"(d[0]), "+f"(d[1]), "+f"(d[2]), "+f"(d[3])
                 : "r"(a0), "r"(a1), "r"(a2), "r"(a3), "r"(b0), "r"(b1));
}

template <int ITERS, int THREADS>
__device__ __forceinline__ void ldg_tile(const float* __restrict__ base, int row0,
                                         int rows_max, int K, int kb, int tid,
                                         float2 v[ITERS]) {
    #pragma unroll
    for (int it = 0; it < ITERS; it++) {
        int idx = tid + it * THREADS;
        int r = idx >> 4, j = idx & 15;
        int gr = row0 + r, gk = kb + 2 * j;
        v[it] = (gr < rows_max && gk < K)
                ? *reinterpret_cast<const float2*>(&base[(size_t)gr * K + gk])
                : make_float2(0.f, 0.f);
    }
}

template <int ITERS, int THREADS>
__device__ __forceinline__ void sts_tile(unsigned* buf, int tid, const float2 v[ITERS]) {
    #pragma unroll
    for (int it = 0; it < ITERS; it++) {
        int idx = tid + it * THREADS;
        int r = idx >> 4, j = idx & 15;
        float2 a = v[it];
        __nv_bfloat16 hx = __float2bfloat16_rn(a.x);
        __nv_bfloat16 hy = __float2bfloat16_rn(a.y);
        float mx = a.x - __bfloat162float(hx);
        float my = a.y - __bfloat162float(hy);
        __nv_bfloat162 hp; hp.x = hx; hp.y = hy;
        unsigned hi = *reinterpret_cast<unsigned*>(&hp);
        unsigned mid = pk_bf2(mx, my);
        *reinterpret_cast<uint2*>(&buf[r * 36 + 2 * j]) = make_uint2(hi, mid);
    }
}

// ---------------- fused conv GEMM: A[N x K] @ Wall[180 x K]^T, 128x192 tile ----
#define FUSED_SMEM_BYTES ((2 * 128 * 36 + 2 * 192 * 36) * 4)

__global__ void __launch_bounds__(512, 1)
gemm_conv_fused(const float* __restrict__ A, const float* __restrict__ Wall,
                const float* __restrict__ ssS, const float* __restrict__ ssH,
                float* __restrict__ Hdst, float* __restrict__ Zr, int N, int K) {
    extern __shared__ unsigned smem_u[];
    unsigned* sA = smem_u;                    // [2][128][36]
    unsigned* sW = smem_u + 2 * 128 * 36;     // [2][192][36]

    const int tid  = threadIdx.x;
    const int lane = tid & 31;
    const int wid  = tid >> 5;
    const int warpM = wid & 3;
    const int warpN = wid >> 2;
    const int row0 = blockIdx.x * 128;
    const int g = lane >> 2;
    const int t = lane & 3;
    const int mBase = warpM * 32;

    float acc[2][6][4];
    #pragma unroll
    for (int mt = 0; mt < 2; mt++)
        #pragma unroll
        for (int nt = 0; nt < 6; nt++)
            #pragma unroll
            for (int j = 0; j < 4; j++) acc[mt][nt][j] = 0.0f;

    float2 aReg[4], wReg[6];
    ldg_tile<4, 512>(A, row0, N, K, 0, tid, aReg);
    ldg_tile<6, 512>(Wall, 0, H3, K, 0, tid, wReg);
    sts_tile<4, 512>(sA, tid, aReg);
    sts_tile<6, 512>(sW, tid, wReg);
    __syncthreads();

    const int nC = (K + 31) / 32;
    for (int c = 0; c < nC; c++) {
        const int cur = c & 1;
        const unsigned* cA = sA + cur * 128 * 36;
        const unsigned* cW = sW + cur * 192 * 36;
        if (c + 1 < nC) {
            ldg_tile<4, 512>(A, row0, N, K, (c + 1) * 32, tid, aReg);
            ldg_tile<6, 512>(Wall, 0, H3, K, (c + 1) * 32, tid, wReg);
        }
        #pragma unroll
        for (int ks = 0; ks < 2; ks++) {
            const int pb = 2 * (8 * ks + t);
            uint2 aF[2][4];
            #pragma unroll
            for (int mt = 0; mt < 2; mt++) {
                const int br = mBase + mt * 16 + g;
                aF[mt][0] = *reinterpret_cast<const uint2*>(&cA[br * 36 + pb]);
                aF[mt][1] = *reinterpret_cast<const uint2*>(&cA[(br + 8) * 36 + pb]);
                aF[mt][2] = *reinterpret_cast<const uint2*>(&cA[br * 36 + pb + 8]);
                aF[mt][3] = *reinterpret_cast<const uint2*>(&cA[(br + 8) * 36 + pb + 8]);
            }
            #pragma unroll
            for (int nt = 0; nt < 6; nt++) {
                const int bn_ = warpN * 48 + nt * 8 + g;
                uint2 b0 = *reinterpret_cast<const uint2*>(&cW[bn_ * 36 + pb]);
                uint2 b1 = *reinterpret_cast<const uint2*>(&cW[bn_ * 36 + pb + 8]);
                #pragma unroll
                for (int mt = 0; mt < 2; mt++) {
                    mma_bf16(acc[mt][nt], aF[mt][0].x, aF[mt][1].x, aF[mt][2].x, aF[mt][3].x, b0.x, b1.x); // hi*hi
                    mma_bf16(acc[mt][nt], aF[mt][0].x, aF[mt][1].x, aF[mt][2].x, aF[mt][3].x, b0.y, b1.y); // hi*mid
                    mma_bf16(acc[mt][nt], aF[mt][0].y, aF[mt][1].y, aF[mt][2].y, aF[mt][3].y, b0.x, b1.x); // mid*hi
                }
            }
        }
        if (c + 1 < nC) {
            sts_tile<4, 512>(sA + ((c + 1) & 1) * 128 * 36, tid, aReg);
            sts_tile<6, 512>(sW + ((c + 1) & 1) * 192 * 36, tid, wReg);
        }
        __syncthreads();
    }

    #pragma unroll
    for (int mt = 0; mt < 2; mt++) {
        const int rlo = row0 + mBase + mt * 16 + g;
        #pragma unroll
        for (int nt = 0; nt < 6; nt++) {
            const int cb = warpN * 48 + nt * 8 + 2 * t;
            #pragma unroll
            for (int jj = 0; jj < 2; jj++) {
                int c = cb + jj;
                if (c >= H3) continue;
                float v0 = acc[mt][nt][jj];
                float v1 = acc[mt][nt][2 + jj];
                if (c < 60) {
                    float sc = ssS[c], sh = ssH[c];
                    if (rlo < N)     Hdst[(size_t)rlo * H3 + c] = v0 * sc + sh;
                    if (rlo + 8 < N) Hdst[(size_t)(rlo + 8) * H3 + c] = v1 * sc + sh;
                } else {
                    int zc = c - 60;
                    if (rlo < N)     Zr[(size_t)rlo * 120 + zc] = v0;
                    if (rlo + 8 < N) Zr[(size_t)(rlo + 8) * 120 + zc] = v1;
                }
            }
        }
    }
}

// ---------------- final linear GEMM (128x64 tile, bias only) ----------------
#define GEMM_SMEM_BYTES ((2 * 128 * 36 + 2 * 64 * 36) * 4)

__global__ void __launch_bounds__(256, 2)
gemm_final(const float* __restrict__ A, const float* __restrict__ W,
           const float* __restrict__ bias, float* __restrict__ outF, int N, int K, int Cc) {
    extern __shared__ unsigned smem_u[];
    unsigned* sA = smem_u;                    // [2][128][36]
    unsigned* sW = smem_u + 2 * 128 * 36;     // [2][64][36]

    const int tid  = threadIdx.x;
    const int lane = tid & 31;
    const int wid  = tid >> 5;
    const int warpM = wid & 3;
    const int warpN = wid >> 2;
    const int row0 = blockIdx.x * 128;
    const int g = lane >> 2;
    const int t = lane & 3;
    const int mBase = warpM * 32;

    float acc[2][4][4];
    #pragma unroll
    for (int mt = 0; mt < 2; mt++)
        #pragma unroll
        for (int nt = 0; nt < 4; nt++)
            #pragma unroll
            for (int j = 0; j < 4; j++) acc[mt][nt][j] = 0.0f;

    float2 aReg[8], wReg[4];
    ldg_tile<8, 256>(A, row0, N, K, 0, tid, aReg);
    ldg_tile<4, 256>(W, 0, Cc, K, 0, tid, wReg);
    sts_tile<8, 256>(sA, tid, aReg);
    sts_tile<4, 256>(sW, tid, wReg);
    __syncthreads();

    const int nC = (K + 31) / 32;
    for (int c = 0; c < nC; c++) {
        const int cur = c & 1;
        const unsigned* cA = sA + cur * 128 * 36;
        const unsigned* cW = sW + cur * 64 * 36;
        if (c + 1 < nC) {
            ldg_tile<8, 256>(A, row0, N, K, (c + 1) * 32, tid, aReg);
            ldg_tile<4, 256>(W, 0, Cc, K, (c + 1) * 32, tid, wReg);
        }
        #pragma unroll
        for (int ks = 0; ks < 2; ks++) {
            const int pb = 2 * (8 * ks + t);
            uint2 aF[2][4];
            #pragma unroll
            for (int mt = 0; mt < 2; mt++) {
                const int br = mBase + mt * 16 + g;
                aF[mt][0] = *reinterpret_cast<const uint2*>(&cA[br * 36 + pb]);
                aF[mt][1] = *reinterpret_cast<const uint2*>(&cA[(br + 8) * 36 + pb]);
                aF[mt][2] = *reinterpret_cast<const uint2*>(&cA[br * 36 + pb + 8]);
                aF[mt][3] = *reinterpret_cast<const uint2*>(&cA[(br + 8) * 36 + pb + 8]);
            }
            #pragma unroll
            for (int nt = 0; nt < 4; nt++) {
                const int bn_ = warpN * 32 + nt * 8 + g;
                uint2 b0 = *reinterpret_cast<const uint2*>(&cW[bn_ * 36 + pb]);
                uint2 b1 = *reinterpret_cast<const uint2*>(&cW[bn_ * 36 + pb + 8]);
                #pragma unroll
                for (int mt = 0; mt < 2; mt++) {
                    mma_bf16(acc[mt][nt], aF[mt][0].x, aF[mt][1].x, aF[mt][2].x, aF[mt][3].x, b0.x, b1.x);
                    mma_bf16(acc[mt][nt], aF[mt][0].x, aF[mt][1].x, aF[mt][2].x, aF[mt][3].x, b0.y, b1.y);
                    mma_bf16(acc[mt][nt], aF[mt][0].y, aF[mt][1].y, aF[mt][2].y, aF[mt][3].y, b0.x, b1.x);
                }
            }
        }
        if (c + 1 < nC) {
            sts_tile<8, 256>(sA + ((c + 1) & 1) * 128 * 36, tid, aReg);
            sts_tile<4, 256>(sW + ((c + 1) & 1) * 64 * 36, tid, wReg);
        }
        __syncthreads();
    }

    #pragma unroll
    for (int mt = 0; mt < 2; mt++) {
        const int rlo = row0 + mBase + mt * 16 + g;
        #pragma unroll
        for (int nt = 0; nt < 4; nt++) {
            const int cb = warpN * 32 + nt * 8 + 2 * t;
            #pragma unroll
            for (int jj = 0; jj < 2; jj++) {
                int c = cb + jj;
                if (c >= Cc) continue;
                float add = bias[c];
                if (rlo < N)     outF[(size_t)rlo * CC + c] = acc[mt][nt][jj] + add;
                if (rlo + 8 < N) outF[(size_t)(rlo + 8) * CC + c] = acc[mt][nt][2 + jj] + add;
            }
        }
    }
}

// ---------------- host launch ----------------
extern "C" void kernel_launch(void* const* d_in, const int* in_sizes, int n_in,
                              void* d_out, int out_size) {
    const float* x       = (const float*)d_in[0];
    const int*   ei      = (const int*)d_in[1];
    const float* conv1_W = (const float*)d_in[2];
    const float* conv1_b = (const float*)d_in[3];
    const float* conv2_W = (const float*)d_in[4];
    const float* conv2_b = (const float*)d_in[5];
    const float* conv3_W = (const float*)d_in[6];
    const float* conv3_b = (const float*)d_in[7];
    const float* bn1_g = (const float*)d_in[8];
    const float* bn1_b = (const float*)d_in[9];
    const float* bn1_m = (const float*)d_in[10];
    const float* bn1_v = (const float*)d_in[11];
    const float* bn2_g = (const float*)d_in[12];
    const float* bn2_b = (const float*)d_in[13];
    const float* bn2_m = (const float*)d_in[14];
    const float* bn2_v = (const float*)d_in[15];
    const float* bn3_g = (const float*)d_in[16];
    const float* bn3_b = (const float*)d_in[17];
    const float* bn3_m = (const float*)d_in[18];
    const float* bn3_v = (const float*)d_in[19];
    const float* lin_W = (const float*)d_in[20];
    const float* lin_b = (const float*)d_in[21];
    float* out = (float*)d_out;

    const int N = in_sizes[0] / DD;
    const int E = in_sizes[1] / 2;

    float *Zr, *Zs, *Ha, *Hb, *enorm, *dis, *sc, *sh;
    int *cnt, *ptr, *cursor, *srcIdx, *blockSum, *blockOff;
    cudaGetSymbolAddress((void**)&Zr, g_Zr);
    cudaGetSymbolAddress((void**)&Zs, g_Zs);
    cudaGetSymbolAddress((void**)&Ha, g_Ha);
    cudaGetSymbolAddress((void**)&Hb, g_Hb);
    cudaGetSymbolAddress((void**)&sc, g_scale);
    cudaGetSymbolAddress((void**)&sh, g_shift);
    cudaGetSymbolAddress((void**)&cnt, g_cnt);
    cudaGetSymbolAddress((void**)&ptr, g_ptr);
    cudaGetSymbolAddress((void**)&cursor, g_cursor);
    cudaGetSymbolAddress((void**)&srcIdx, g_srcIdx);
    cudaGetSymbolAddress((void**)&enorm, g_enorm);
    cudaGetSymbolAddress((void**)&dis, g_dis);
    cudaGetSymbolAddress((void**)&blockSum, g_blockSum);
    cudaGetSymbolAddress((void**)&blockOff, g_blockOff);

    cudaFuncSetAttribute(gemm_conv_fused,
                         cudaFuncAttributeMaxDynamicSharedMemorySize, FUSED_SMEM_BYTES);
    cudaFuncSetAttribute(gemm_final,
                         cudaFuncAttributeMaxDynamicSharedMemorySize, GEMM_SMEM_BYTES);

    // side stream + fork/join events (created once, pre-capture on the
    // correctness call; reused identically on every call thereafter)
    static cudaStream_t s2 = nullptr;
    static cudaEvent_t evFork = nullptr, evCsr = nullptr;
    if (s2 == nullptr) {
        cudaStreamCreateWithFlags(&s2, cudaStreamNonBlocking);
        cudaEventCreateWithFlags(&evFork, cudaEventDisableTiming);
        cudaEventCreateWithFlags(&evCsr, cudaEventDisableTiming);
    }

    const int* e_row = ei;
    const int* e_col = ei + E;
    const int nScanBlocks = (N + 255) / 256;

    // ---- fork: CSR build on s2, projection path on default stream ----
    cudaEventRecord(evFork, 0);
    cudaStreamWaitEvent(s2, evFork, 0);

    // s2: CSR build (parallel scan)
    cudaMemsetAsync(cnt, 0, N * sizeof(int), s2);
    hist_kernel<<<(E + 255) / 256, 256, 0, s2>>>(e_col, cnt, E);
    partial_kernel<<<nScanBlocks, 256, 0, s2>>>(cnt, blockSum, N);
    scanblk_kernel<<<1, 256, 0, s2>>>(blockSum, blockOff, nScanBlocks);
    scanwrite_kernel<<<nScanBlocks, 256, 0, s2>>>(cnt, blockOff, ptr, cursor, dis, N);
    scatter_kernel<<<(E + 255) / 256, 256, 0, s2>>>(e_row, e_col, dis, cursor, srcIdx, enorm, E);
    cudaEventRecord(evCsr, s2);

    // default: folded scale/shift + layer-1 projection GEMM (no CSR dependency)
    ss_all_kernel<<<3, H3>>>(conv1_b, bn1_g, bn1_b, bn1_m, bn1_v,
                             conv2_b, bn2_g, bn2_b, bn2_m, bn2_v,
                             conv3_b, bn3_g, bn3_b, bn3_m, bn3_v, sc, sh);

    const int gemmBlocks = (N + 127) / 128;
    const int h1Blocks = (N + 7) / 8;
    const int h2Blocks = (N + 15) / 16;

    gemm_conv_fused<<<gemmBlocks, 512, FUSED_SMEM_BYTES>>>(x, conv1_W, sc, sh, Ha, Zr, N, DD);

    // ---- join: SpMM needs CSR ----
    cudaStreamWaitEvent(0, evCsr, 0);

    // ---- layer 1 aggregation ----
    spmm_h1<<<h1Blocks, 256>>>((const float4*)Zr, (float4*)Ha, (float4*)Zs,
                               ptr, srcIdx, enorm, dis, sc + 60, sh + 60, N);
    spmm_h2<<<h2Blocks, 256>>>((const float4*)Zs, (float4*)Ha,
                               ptr, srcIdx, enorm, dis, sc + 120, sh + 120, N);

    // ---- layer 2 (K=180) ----
    gemm_conv_fused<<<gemmBlocks, 512, FUSED_SMEM_BYTES>>>(Ha, conv2_W, sc + H3, sh + H3,
                                                           Hb, Zr, N, H3);
    spmm_h1<<<h1Blocks, 256>>>((const float4*)Zr, (float4*)Hb, (float4*)Zs,
                               ptr, srcIdx, enorm, dis, sc + H3 + 60, sh + H3 + 60, N);
    spmm_h2<<<h2Blocks, 256>>>((const float4*)Zs, (float4*)Hb,
                               ptr, srcIdx, enorm, dis, sc + H3 + 120, sh + H3 + 120, N);

    // ---- layer 3 (K=180) ----
    gemm_conv_fused<<<gemmBlocks, 512, FUSED_SMEM_BYTES>>>(Hb, conv3_W,
                                                           sc + 2 * H3, sh + 2 * H3,
                                                           Ha, Zr, N, H3);
    spmm_h1<<<h1Blocks, 256>>>((const float4*)Zr, (float4*)Ha, (float4*)Zs,
                               ptr, srcIdx, enorm, dis, sc + 2 * H3 + 60, sh + 2 * H3 + 60, N);
    spmm_h2<<<h2Blocks, 256>>>((const float4*)Zs, (float4*)Ha,
                               ptr, srcIdx, enorm, dis, sc + 2 * H3 + 120, sh + 2 * H3 + 120, N);

    // ---- final linear ----
    gemm_final<<<gemmBlocks, 256, GEMM_SMEM_BYTES>>>(Ha, lin_W, lin_b, out, N, H3, CC);
}

// round 13
// speedup vs baseline: 2.8126x; 1.1404x over previous
#include <cuda_runtime.h>
#include <cuda_bf16.h>
#include <cuda_fp16.h>

// ---------------- problem constants ----------------
#define NN 50000
#define EE 400000
#define DD 128
#define HH 60
#define H3 180
#define CC 40
#define BN_EPS 1e-5f

// ---------------- static scratch ----------------
__device__ __half g_Zr16[NN * 120];   // raw p=1,2 projections (fp16)
__device__ __half g_Zs16[NN * 64];    // raw hop-1 result for p=2 (fp16)
__device__ float g_Ha[NN * H3];
__device__ float g_Hb[NN * H3];
__device__ float g_scale[3 * H3];
__device__ float g_shift[3 * H3];
__device__ int   g_cnt[NN];
__device__ int   g_ptr[NN + 1];
__device__ int   g_cursor[NN];
__device__ int   g_blockSum[256];
__device__ int   g_blockOff[256];
__device__ int   g_srcIdx[EE];
__device__ float g_enorm[EE];
__device__ float g_dis[NN];

// ---------------- CSR build ----------------
__global__ void hist_kernel(const int* __restrict__ col, int* __restrict__ cnt, int E) {
    int e = blockIdx.x * blockDim.x + threadIdx.x;
    if (e < E) atomicAdd(&cnt[col[e]], 1);
}

__global__ void partial_kernel(const int* __restrict__ cnt, int* __restrict__ blockSum, int n) {
    __shared__ int ws[8];
    int i = blockIdx.x * 256 + threadIdx.x;
    int lane = threadIdx.x & 31, wid = threadIdx.x >> 5;
    int v = (i < n) ? cnt[i] : 0;
    #pragma unroll
    for (int off = 16; off > 0; off >>= 1) v += __shfl_down_sync(0xffffffffu, v, off);
    if (lane == 0) ws[wid] = v;
    __syncthreads();
    if (wid == 0) {
        int s = (lane < 8) ? ws[lane] : 0;
        #pragma unroll
        for (int off = 4; off > 0; off >>= 1) s += __shfl_down_sync(0xffffffffu, s, off);
        if (lane == 0) blockSum[blockIdx.x] = s;
    }
}

__global__ void scanblk_kernel(const int* __restrict__ blockSum, int* __restrict__ blockOff,
                               int nBlocks) {
    __shared__ int ws[8];
    int lane = threadIdx.x & 31, wid = threadIdx.x >> 5;
    int v = (threadIdx.x < nBlocks) ? blockSum[threadIdx.x] : 0;
    int x = v;
    #pragma unroll
    for (int off = 1; off < 32; off <<= 1) {
        int t = __shfl_up_sync(0xffffffffu, x, off);
        if (lane >= off) x += t;
    }
    if (lane == 31) ws[wid] = x;
    __syncthreads();
    if (wid == 0 && lane < 8) {
        int w = ws[lane];
        #pragma unroll
        for (int off = 1; off < 8; off <<= 1) {
            int t = __shfl_up_sync(0xffu, w, off);
            if (lane >= off) w += t;
        }
        ws[lane] = w;
    }
    __syncthreads();
    int woff = wid ? ws[wid - 1] : 0;
    if (threadIdx.x < nBlocks) blockOff[threadIdx.x] = woff + x - v;
}

__global__ void scanwrite_kernel(const int* __restrict__ cnt, const int* __restrict__ blockOff,
                                 int* __restrict__ ptr, int* __restrict__ cursor,
                                 float* __restrict__ dis, int n) {
    __shared__ int ws[8];
    int i = blockIdx.x * 256 + threadIdx.x;
    int lane = threadIdx.x & 31, wid = threadIdx.x >> 5;
    int v = (i < n) ? cnt[i] : 0;
    int x = v;
    #pragma unroll
    for (int off = 1; off < 32; off <<= 1) {
        int t = __shfl_up_sync(0xffffffffu, x, off);
        if (lane >= off) x += t;
    }
    if (lane == 31) ws[wid] = x;
    __syncthreads();
    if (wid == 0 && lane < 8) {
        int w = ws[lane];
        #pragma unroll
        for (int off = 1; off < 8; off <<= 1) {
            int t = __shfl_up_sync(0xffu, w, off);
            if (lane >= off) w += t;
        }
        ws[lane] = w;
    }
    __syncthreads();
    int woff = wid ? ws[wid - 1] : 0;
    int excl = blockOff[blockIdx.x] + woff + x - v;
    if (i < n) {
        ptr[i] = excl;
        cursor[i] = excl;
        dis[i] = rsqrtf((float)(v + 1));   // +1 self loop
        if (i == n - 1) ptr[n] = excl + v;
    }
}

__global__ void scatter_kernel(const int* __restrict__ row, const int* __restrict__ col,
                               const float* __restrict__ dis, int* __restrict__ cursor,
                               int* __restrict__ srcIdx, float* __restrict__ enorm, int E) {
    int e = blockIdx.x * blockDim.x + threadIdx.x;
    if (e < E) {
        int r = row[e], c = col[e];
        int pos = atomicAdd(&cursor[c], 1);
        srcIdx[pos] = r;
        enorm[pos]  = dis[r] * dis[c];
    }
}

// ---------------- folded BN scale/shift precompute ----------------
__global__ void ss_all_kernel(const float* __restrict__ b1c, const float* __restrict__ g1,
                              const float* __restrict__ b1, const float* __restrict__ m1,
                              const float* __restrict__ v1,
                              const float* __restrict__ b2c, const float* __restrict__ g2,
                              const float* __restrict__ b2, const float* __restrict__ m2,
                              const float* __restrict__ v2,
                              const float* __restrict__ b3c, const float* __restrict__ g3,
                              const float* __restrict__ b3, const float* __restrict__ m3,
                              const float* __restrict__ v3,
                              float* __restrict__ sc, float* __restrict__ sh) {
    int L = blockIdx.x;
    int c = threadIdx.x;
    if (c >= H3) return;
    const float* cb = (L == 0) ? b1c : (L == 1) ? b2c : b3c;
    const float* g  = (L == 0) ? g1  : (L == 1) ? g2  : g3;
    const float* b  = (L == 0) ? b1  : (L == 1) ? b2  : b3;
    const float* m  = (L == 0) ? m1  : (L == 1) ? m2  : m3;
    const float* v  = (L == 0) ? v1  : (L == 1) ? v2  : v3;
    float s = g[c] * rsqrtf(v[c] + BN_EPS);
    sc[L * H3 + c] = s;
    sh[L * H3 + c] = (cb[c] - m[c]) * s + b[c];
}

// ---------------- fp16 gather helpers ----------------
__device__ __forceinline__ float4 h4_to_f4(uint2 raw) {
    __half2 p0 = *reinterpret_cast<__half2*>(&raw.x);
    __half2 p1 = *reinterpret_cast<__half2*>(&raw.y);
    float2 f0 = __half22float2(p0);
    float2 f1 = __half22float2(p1);
    return make_float4(f0.x, f0.y, f1.x, f1.y);
}

__device__ __forceinline__ uint2 f4_to_h4(float4 v) {
    __half2 p0 = __floats2half2_rn(v.x, v.y);
    __half2 p1 = __floats2half2_rn(v.z, v.w);
    uint2 r;
    r.x = *reinterpret_cast<unsigned*>(&p0);
    r.y = *reinterpret_cast<unsigned*>(&p1);
    return r;
}

// ---------------- SpMM hop 1: 120-wide fp16 gather (4-edge unroll) ----------------
// Zr2: uint2 rows of 30 (120 halfs). lanes 0-14 -> H[:,60:120] fp32 finalized;
// lanes 15-29 -> Zs fp16 raw.
__global__ void __launch_bounds__(256)
spmm_h1(const uint2* __restrict__ Zr2, float4* __restrict__ H, uint2* __restrict__ Zs2,
        const int* __restrict__ ptr, const int* __restrict__ srcIdx,
        const float* __restrict__ enorm, const float* __restrict__ dis,
        const float* __restrict__ ssS, const float* __restrict__ ssH, int N) {
    const int lane = threadIdx.x & 31;
    const int node = blockIdx.x * 8 + (threadIdx.x >> 5);
    if (node >= N) return;
    const bool act = lane < 30;

    float d = dis[node];
    float dd = d * d;
    float4 acc = make_float4(0.f, 0.f, 0.f, 0.f);
    if (act) {
        float4 v = h4_to_f4(Zr2[node * 30 + lane]);
        acc.x = dd * v.x; acc.y = dd * v.y; acc.z = dd * v.z; acc.w = dd * v.w;
    }

    int s = ptr[node], e = ptr[node + 1];
    int k = s;
    for (; k + 3 < e; k += 4) {
        int s0 = srcIdx[k], s1 = srcIdx[k + 1], s2 = srcIdx[k + 2], s3 = srcIdx[k + 3];
        float w0 = enorm[k], w1 = enorm[k + 1], w2 = enorm[k + 2], w3 = enorm[k + 3];
        if (act) {
            float4 v0 = h4_to_f4(Zr2[s0 * 30 + lane]);
            float4 v1 = h4_to_f4(Zr2[s1 * 30 + lane]);
            float4 v2 = h4_to_f4(Zr2[s2 * 30 + lane]);
            float4 v3 = h4_to_f4(Zr2[s3 * 30 + lane]);
            acc.x += w0 * v0.x; acc.y += w0 * v0.y; acc.z += w0 * v0.z; acc.w += w0 * v0.w;
            acc.x += w1 * v1.x; acc.y += w1 * v1.y; acc.z += w1 * v1.z; acc.w += w1 * v1.w;
            acc.x += w2 * v2.x; acc.y += w2 * v2.y; acc.z += w2 * v2.z; acc.w += w2 * v2.w;
            acc.x += w3 * v3.x; acc.y += w3 * v3.y; acc.z += w3 * v3.z; acc.w += w3 * v3.w;
        }
    }
    for (; k < e; k++) {
        int s0 = srcIdx[k];
        float w0 = enorm[k];
        if (act) {
            float4 v0 = h4_to_f4(Zr2[s0 * 30 + lane]);
            acc.x += w0 * v0.x; acc.y += w0 * v0.y; acc.z += w0 * v0.z; acc.w += w0 * v0.w;
        }
    }

    if (lane < 15) {
        float4 sc = reinterpret_cast<const float4*>(ssS)[lane];
        float4 sh = reinterpret_cast<const float4*>(ssH)[lane];
        float4 o;
        o.x = acc.x * sc.x + sh.x;
        o.y = acc.y * sc.y + sh.y;
        o.z = acc.z * sc.z + sh.z;
        o.w = acc.w * sc.w + sh.w;
        H[node * 45 + 15 + lane] = o;                // H[:, 60:120] fp32
    } else if (act) {
        Zs2[node * 15 + (lane - 15)] = f4_to_h4(acc); // raw p=2 hop-1 fp16
    }
}

// ---------------- SpMM hop 2: 60-wide fp16 gather (4-edge unroll) ----------------
__global__ void __launch_bounds__(256)
spmm_h2(const uint2* __restrict__ Zs2, float4* __restrict__ H,
        const int* __restrict__ ptr, const int* __restrict__ srcIdx,
        const float* __restrict__ enorm, const float* __restrict__ dis,
        const float* __restrict__ ssS, const float* __restrict__ ssH, int N) {
    const int l = threadIdx.x & 15;
    const int node = blockIdx.x * 16 + (threadIdx.x >> 4);
    if (node >= N) return;
    const bool act = l < 15;

    float d = dis[node];
    float dd = d * d;
    float4 acc = make_float4(0.f, 0.f, 0.f, 0.f);
    if (act) {
        float4 v = h4_to_f4(Zs2[node * 15 + l]);
        acc.x = dd * v.x; acc.y = dd * v.y; acc.z = dd * v.z; acc.w = dd * v.w;
    }

    int s = ptr[node], e = ptr[node + 1];
    int k = s;
    for (; k + 3 < e; k += 4) {
        int s0 = srcIdx[k], s1 = srcIdx[k + 1], s2 = srcIdx[k + 2], s3 = srcIdx[k + 3];
        float w0 = enorm[k], w1 = enorm[k + 1], w2 = enorm[k + 2], w3 = enorm[k + 3];
        if (act) {
            float4 v0 = h4_to_f4(Zs2[s0 * 15 + l]);
            float4 v1 = h4_to_f4(Zs2[s1 * 15 + l]);
            float4 v2 = h4_to_f4(Zs2[s2 * 15 + l]);
            float4 v3 = h4_to_f4(Zs2[s3 * 15 + l]);
            acc.x += w0 * v0.x; acc.y += w0 * v0.y; acc.z += w0 * v0.z; acc.w += w0 * v0.w;
            acc.x += w1 * v1.x; acc.y += w1 * v1.y; acc.z += w1 * v1.z; acc.w += w1 * v1.w;
            acc.x += w2 * v2.x; acc.y += w2 * v2.y; acc.z += w2 * v2.z; acc.w += w2 * v2.w;
            acc.x += w3 * v3.x; acc.y += w3 * v3.y; acc.z += w3 * v3.z; acc.w += w3 * v3.w;
        }
    }
    for (; k < e; k++) {
        int s0 = srcIdx[k];
        float w0 = enorm[k];
        if (act) {
            float4 v0 = h4_to_f4(Zs2[s0 * 15 + l]);
            acc.x += w0 * v0.x; acc.y += w0 * v0.y; acc.z += w0 * v0.z; acc.w += w0 * v0.w;
        }
    }

    if (act) {
        float4 sc = reinterpret_cast<const float4*>(ssS)[l];
        float4 sh = reinterpret_cast<const float4*>(ssH)[l];
        float4 o;
        o.x = acc.x * sc.x + sh.x;
        o.y = acc.y * sc.y + sh.y;
        o.z = acc.z * sc.z + sh.z;
        o.w = acc.w * sc.w + sh.w;
        H[node * 45 + 30 + l] = o;          // H[:, 120:180] fp32
    }
}

// ---------------- bf16 split helpers ----------------
__device__ __forceinline__ unsigned pk_bf2(float x, float y) {
    __nv_bfloat162 p = __floats2bfloat162_rn(x, y);
    return *reinterpret_cast<unsigned*>(&p);
}

__device__ __forceinline__ void mma_bf16(float* d, unsigned a0, unsigned a1,
                                         unsigned a2, unsigned a3,
                                         unsigned b0, unsigned b1) {
    asm volatile("mma.sync.aligned.m16n8k16.row.col.f32.bf16.bf16.f32 "
                 "{%0,%1,%2,%3}, {%4,%5,%6,%7}, {%8,%9}, {%0,%1,%2,%3};"
                 : "+f"(d[0]), "+f"(d[1]), "+f"(d[2]), "+f"(d[3])
                 : "r"(a0), "r"(a1), "r"(a2), "r"(a3), "r"(b0), "r"(b1));
}

template <int ITERS, int THREADS>
__device__ __forceinline__ void ldg_tile(const float* __restrict__ base, int row0,
                                         int rows_max, int K, int kb, int tid,
                                         float2 v[ITERS]) {
    #pragma unroll
    for (int it = 0; it < ITERS; it++) {
        int idx = tid + it * THREADS;
        int r = idx >> 4, j = idx & 15;
        int gr = row0 + r, gk = kb + 2 * j;
        v[it] = (gr < rows_max && gk < K)
                ? *reinterpret_cast<const float2*>(&base[(size_t)gr * K + gk])
                : make_float2(0.f, 0.f);
    }
}

template <int ITERS, int THREADS>
__device__ __forceinline__ void sts_tile(unsigned* buf, int tid, const float2 v[ITERS]) {
    #pragma unroll
    for (int it = 0; it < ITERS; it++) {
        int idx = tid + it * THREADS;
        int r = idx >> 4, j = idx & 15;
        float2 a = v[it];
        __nv_bfloat16 hx = __float2bfloat16_rn(a.x);
        __nv_bfloat16 hy = __float2bfloat16_rn(a.y);
        float mx = a.x - __bfloat162float(hx);
        float my = a.y - __bfloat162float(hy);
        __nv_bfloat162 hp; hp.x = hx; hp.y = hy;
        unsigned hi = *reinterpret_cast<unsigned*>(&hp);
        unsigned mid = pk_bf2(mx, my);
        *reinterpret_cast<uint2*>(&buf[r * 36 + 2 * j]) = make_uint2(hi, mid);
    }
}

// ---------------- fused conv GEMM: A[N x K] @ Wall[180 x K]^T, 128x192 tile ----
// cols 0:60 -> fp32 finalized Hdst[:,0:60]; cols 60:180 -> fp16 raw Zr.
#define FUSED_SMEM_BYTES ((2 * 128 * 36 + 2 * 192 * 36) * 4)

__global__ void __launch_bounds__(512, 1)
gemm_conv_fused(const float* __restrict__ A, const float* __restrict__ Wall,
                const float* __restrict__ ssS, const float* __restrict__ ssH,
                float* __restrict__ Hdst, __half2* __restrict__ Zr, int N, int K) {
    extern __shared__ unsigned smem_u[];
    unsigned* sA = smem_u;                    // [2][128][36]
    unsigned* sW = smem_u + 2 * 128 * 36;     // [2][192][36]

    const int tid  = threadIdx.x;
    const int lane = tid & 31;
    const int wid  = tid >> 5;
    const int warpM = wid & 3;
    const int warpN = wid >> 2;
    const int row0 = blockIdx.x * 128;
    const int g = lane >> 2;
    const int t = lane & 3;
    const int mBase = warpM * 32;

    float acc[2][6][4];
    #pragma unroll
    for (int mt = 0; mt < 2; mt++)
        #pragma unroll
        for (int nt = 0; nt < 6; nt++)
            #pragma unroll
            for (int j = 0; j < 4; j++) acc[mt][nt][j] = 0.0f;

    float2 aReg[4], wReg[6];
    ldg_tile<4, 512>(A, row0, N, K, 0, tid, aReg);
    ldg_tile<6, 512>(Wall, 0, H3, K, 0, tid, wReg);
    sts_tile<4, 512>(sA, tid, aReg);
    sts_tile<6, 512>(sW, tid, wReg);
    __syncthreads();

    const int nC = (K + 31) / 32;
    for (int c = 0; c < nC; c++) {
        const int cur = c & 1;
        const unsigned* cA = sA + cur * 128 * 36;
        const unsigned* cW = sW + cur * 192 * 36;
        if (c + 1 < nC) {
            ldg_tile<4, 512>(A, row0, N, K, (c + 1) * 32, tid, aReg);
            ldg_tile<6, 512>(Wall, 0, H3, K, (c + 1) * 32, tid, wReg);
        }
        #pragma unroll
        for (int ks = 0; ks < 2; ks++) {
            const int pb = 2 * (8 * ks + t);
            uint2 aF[2][4];
            #pragma unroll
            for (int mt = 0; mt < 2; mt++) {
                const int br = mBase + mt * 16 + g;
                aF[mt][0] = *reinterpret_cast<const uint2*>(&cA[br * 36 + pb]);
                aF[mt][1] = *reinterpret_cast<const uint2*>(&cA[(br + 8) * 36 + pb]);
                aF[mt][2] = *reinterpret_cast<const uint2*>(&cA[br * 36 + pb + 8]);
                aF[mt][3] = *reinterpret_cast<const uint2*>(&cA[(br + 8) * 36 + pb + 8]);
            }
            #pragma unroll
            for (int nt = 0; nt < 6; nt++) {
                const int bn_ = warpN * 48 + nt * 8 + g;
                uint2 b0 = *reinterpret_cast<const uint2*>(&cW[bn_ * 36 + pb]);
                uint2 b1 = *reinterpret_cast<const uint2*>(&cW[bn_ * 36 + pb + 8]);
                #pragma unroll
                for (int mt = 0; mt < 2; mt++) {
                    mma_bf16(acc[mt][nt], aF[mt][0].x, aF[mt][1].x, aF[mt][2].x, aF[mt][3].x, b0.x, b1.x); // hi*hi
                    mma_bf16(acc[mt][nt], aF[mt][0].x, aF[mt][1].x, aF[mt][2].x, aF[mt][3].x, b0.y, b1.y); // hi*mid
                    mma_bf16(acc[mt][nt], aF[mt][0].y, aF[mt][1].y, aF[mt][2].y, aF[mt][3].y, b0.x, b1.x); // mid*hi
                }
            }
        }
        if (c + 1 < nC) {
            sts_tile<4, 512>(sA + ((c + 1) & 1) * 128 * 36, tid, aReg);
            sts_tile<6, 512>(sW + ((c + 1) & 1) * 192 * 36, tid, wReg);
        }
        __syncthreads();
    }

    #pragma unroll
    for (int mt = 0; mt < 2; mt++) {
        const int rlo = row0 + mBase + mt * 16 + g;
        #pragma unroll
        for (int nt = 0; nt < 6; nt++) {
            const int c0 = warpN * 48 + nt * 8 + 2 * t;   // even; pair (c0, c0+1)
            if (c0 >= H3) continue;
            if (c0 < 60) {
                #pragma unroll
                for (int jj = 0; jj < 2; jj++) {
                    int c = c0 + jj;
                    float sc = ssS[c], sh = ssH[c];
                    if (rlo < N)     Hdst[(size_t)rlo * H3 + c] = acc[mt][nt][jj] * sc + sh;
                    if (rlo + 8 < N) Hdst[(size_t)(rlo + 8) * H3 + c] = acc[mt][nt][2 + jj] * sc + sh;
                }
            } else {
                int zc = (c0 - 60) >> 1;   // half2 index, 60 per row
                __half2 h0 = __floats2half2_rn(acc[mt][nt][0], acc[mt][nt][1]);
                __half2 h1 = __floats2half2_rn(acc[mt][nt][2], acc[mt][nt][3]);
                if (rlo < N)     Zr[(size_t)rlo * 60 + zc] = h0;
                if (rlo + 8 < N) Zr[(size_t)(rlo + 8) * 60 + zc] = h1;
            }
        }
    }
}

// ---------------- final linear GEMM (128x64 tile, bias only) ----------------
#define GEMM_SMEM_BYTES ((2 * 128 * 36 + 2 * 64 * 36) * 4)

__global__ void __launch_bounds__(256, 2)
gemm_final(const float* __restrict__ A, const float* __restrict__ W,
           const float* __restrict__ bias, float* __restrict__ outF, int N, int K, int Cc) {
    extern __shared__ unsigned smem_u[];
    unsigned* sA = smem_u;                    // [2][128][36]
    unsigned* sW = smem_u + 2 * 128 * 36;     // [2][64][36]

    const int tid  = threadIdx.x;
    const int lane = tid & 31;
    const int wid  = tid >> 5;
    const int warpM = wid & 3;
    const int warpN = wid >> 2;
    const int row0 = blockIdx.x * 128;
    const int g = lane >> 2;
    const int t = lane & 3;
    const int mBase = warpM * 32;

    float acc[2][4][4];
    #pragma unroll
    for (int mt = 0; mt < 2; mt++)
        #pragma unroll
        for (int nt = 0; nt < 4; nt++)
            #pragma unroll
            for (int j = 0; j < 4; j++) acc[mt][nt][j] = 0.0f;

    float2 aReg[8], wReg[4];
    ldg_tile<8, 256>(A, row0, N, K, 0, tid, aReg);
    ldg_tile<4, 256>(W, 0, Cc, K, 0, tid, wReg);
    sts_tile<8, 256>(sA, tid, aReg);
    sts_tile<4, 256>(sW, tid, wReg);
    __syncthreads();

    const int nC = (K + 31) / 32;
    for (int c = 0; c < nC; c++) {
        const int cur = c & 1;
        const unsigned* cA = sA + cur * 128 * 36;
        const unsigned* cW = sW + cur * 64 * 36;
        if (c + 1 < nC) {
            ldg_tile<8, 256>(A, row0, N, K, (c + 1) * 32, tid, aReg);
            ldg_tile<4, 256>(W, 0, Cc, K, (c + 1) * 32, tid, wReg);
        }
        #pragma unroll
        for (int ks = 0; ks < 2; ks++) {
            const int pb = 2 * (8 * ks + t);
            uint2 aF[2][4];
            #pragma unroll
            for (int mt = 0; mt < 2; mt++) {
                const int br = mBase + mt * 16 + g;
                aF[mt][0] = *reinterpret_cast<const uint2*>(&cA[br * 36 + pb]);
                aF[mt][1] = *reinterpret_cast<const uint2*>(&cA[(br + 8) * 36 + pb]);
                aF[mt][2] = *reinterpret_cast<const uint2*>(&cA[br * 36 + pb + 8]);
                aF[mt][3] = *reinterpret_cast<const uint2*>(&cA[(br + 8) * 36 + pb + 8]);
            }
            #pragma unroll
            for (int nt = 0; nt < 4; nt++) {
                const int bn_ = warpN * 32 + nt * 8 + g;
                uint2 b0 = *reinterpret_cast<const uint2*>(&cW[bn_ * 36 + pb]);
                uint2 b1 = *reinterpret_cast<const uint2*>(&cW[bn_ * 36 + pb + 8]);
                #pragma unroll
                for (int mt = 0; mt < 2; mt++) {
                    mma_bf16(acc[mt][nt], aF[mt][0].x, aF[mt][1].x, aF[mt][2].x, aF[mt][3].x, b0.x, b1.x);
                    mma_bf16(acc[mt][nt], aF[mt][0].x, aF[mt][1].x, aF[mt][2].x, aF[mt][3].x, b0.y, b1.y);
                    mma_bf16(acc[mt][nt], aF[mt][0].y, aF[mt][1].y, aF[mt][2].y, aF[mt][3].y, b0.x, b1.x);
                }
            }
        }
        if (c + 1 < nC) {
            sts_tile<8, 256>(sA + ((c + 1) & 1) * 128 * 36, tid, aReg);
            sts_tile<4, 256>(sW + ((c + 1) & 1) * 64 * 36, tid, wReg);
        }
        __syncthreads();
    }

    #pragma unroll
    for (int mt = 0; mt < 2; mt++) {
        const int rlo = row0 + mBase + mt * 16 + g;
        #pragma unroll
        for (int nt = 0; nt < 4; nt++) {
            const int cb = warpN * 32 + nt * 8 + 2 * t;
            #pragma unroll
            for (int jj = 0; jj < 2; jj++) {
                int c = cb + jj;
                if (c >= Cc) continue;
                float add = bias[c];
                if (rlo < N)     outF[(size_t)rlo * CC + c] = acc[mt][nt][jj] + add;
                if (rlo + 8 < N) outF[(size_t)(rlo + 8) * CC + c] = acc[mt][nt][2 + jj] + add;
            }
        }
    }
}

// ---------------- host launch ----------------
extern "C" void kernel_launch(void* const* d_in, const int* in_sizes, int n_in,
                              void* d_out, int out_size) {
    const float* x       = (const float*)d_in[0];
    const int*   ei      = (const int*)d_in[1];
    const float* conv1_W = (const float*)d_in[2];
    const float* conv1_b = (const float*)d_in[3];
    const float* conv2_W = (const float*)d_in[4];
    const float* conv2_b = (const float*)d_in[5];
    const float* conv3_W = (const float*)d_in[6];
    const float* conv3_b = (const float*)d_in[7];
    const float* bn1_g = (const float*)d_in[8];
    const float* bn1_b = (const float*)d_in[9];
    const float* bn1_m = (const float*)d_in[10];
    const float* bn1_v = (const float*)d_in[11];
    const float* bn2_g = (const float*)d_in[12];
    const float* bn2_b = (const float*)d_in[13];
    const float* bn2_m = (const float*)d_in[14];
    const float* bn2_v = (const float*)d_in[15];
    const float* bn3_g = (const float*)d_in[16];
    const float* bn3_b = (const float*)d_in[17];
    const float* bn3_m = (const float*)d_in[18];
    const float* bn3_v = (const float*)d_in[19];
    const float* lin_W = (const float*)d_in[20];
    const float* lin_b = (const float*)d_in[21];
    float* out = (float*)d_out;

    const int N = in_sizes[0] / DD;
    const int E = in_sizes[1] / 2;

    float *Ha, *Hb, *enorm, *dis, *sc, *sh;
    __half *Zr16, *Zs16;
    int *cnt, *ptr, *cursor, *srcIdx, *blockSum, *blockOff;
    cudaGetSymbolAddress((void**)&Zr16, g_Zr16);
    cudaGetSymbolAddress((void**)&Zs16, g_Zs16);
    cudaGetSymbolAddress((void**)&Ha, g_Ha);
    cudaGetSymbolAddress((void**)&Hb, g_Hb);
    cudaGetSymbolAddress((void**)&sc, g_scale);
    cudaGetSymbolAddress((void**)&sh, g_shift);
    cudaGetSymbolAddress((void**)&cnt, g_cnt);
    cudaGetSymbolAddress((void**)&ptr, g_ptr);
    cudaGetSymbolAddress((void**)&cursor, g_cursor);
    cudaGetSymbolAddress((void**)&srcIdx, g_srcIdx);
    cudaGetSymbolAddress((void**)&enorm, g_enorm);
    cudaGetSymbolAddress((void**)&dis, g_dis);
    cudaGetSymbolAddress((void**)&blockSum, g_blockSum);
    cudaGetSymbolAddress((void**)&blockOff, g_blockOff);

    cudaFuncSetAttribute(gemm_conv_fused,
                         cudaFuncAttributeMaxDynamicSharedMemorySize, FUSED_SMEM_BYTES);
    cudaFuncSetAttribute(gemm_final,
                         cudaFuncAttributeMaxDynamicSharedMemorySize, GEMM_SMEM_BYTES);

    // side stream + fork/join events (created once, pre-capture)
    static cudaStream_t s2 = nullptr;
    static cudaEvent_t evFork = nullptr, evCsr = nullptr;
    if (s2 == nullptr) {
        cudaStreamCreateWithFlags(&s2, cudaStreamNonBlocking);
        cudaEventCreateWithFlags(&evFork, cudaEventDisableTiming);
        cudaEventCreateWithFlags(&evCsr, cudaEventDisableTiming);
    }

    const int* e_row = ei;
    const int* e_col = ei + E;
    const int nScanBlocks = (N + 255) / 256;

    // ---- fork: CSR build on s2, projection path on default stream ----
    cudaEventRecord(evFork, 0);
    cudaStreamWaitEvent(s2, evFork, 0);

    cudaMemsetAsync(cnt, 0, N * sizeof(int), s2);
    hist_kernel<<<(E + 255) / 256, 256, 0, s2>>>(e_col, cnt, E);
    partial_kernel<<<nScanBlocks, 256, 0, s2>>>(cnt, blockSum, N);
    scanblk_kernel<<<1, 256, 0, s2>>>(blockSum, blockOff, nScanBlocks);
    scanwrite_kernel<<<nScanBlocks, 256, 0, s2>>>(cnt, blockOff, ptr, cursor, dis, N);
    scatter_kernel<<<(E + 255) / 256, 256, 0, s2>>>(e_row, e_col, dis, cursor, srcIdx, enorm, E);
    cudaEventRecord(evCsr, s2);

    ss_all_kernel<<<3, H3>>>(conv1_b, bn1_g, bn1_b, bn1_m, bn1_v,
                             conv2_b, bn2_g, bn2_b, bn2_m, bn2_v,
                             conv3_b, bn3_g, bn3_b, bn3_m, bn3_v, sc, sh);

    const int gemmBlocks = (N + 127) / 128;
    const int h1Blocks = (N + 7) / 8;
    const int h2Blocks = (N + 15) / 16;

    gemm_conv_fused<<<gemmBlocks, 512, FUSED_SMEM_BYTES>>>(x, conv1_W, sc, sh,
                                                           Ha, (__half2*)Zr16, N, DD);

    // ---- join: SpMM needs CSR ----
    cudaStreamWaitEvent(0, evCsr, 0);

    // ---- layer 1 aggregation ----
    spmm_h1<<<h1Blocks, 256>>>((const uint2*)Zr16, (float4*)Ha, (uint2*)Zs16,
                               ptr, srcIdx, enorm, dis, sc + 60, sh + 60, N);
    spmm_h2<<<h2Blocks, 256>>>((const uint2*)Zs16, (float4*)Ha,
                               ptr, srcIdx, enorm, dis, sc + 120, sh + 120, N);

    // ---- layer 2 (K=180) ----
    gemm_conv_fused<<<gemmBlocks, 512, FUSED_SMEM_BYTES>>>(Ha, conv2_W, sc + H3, sh + H3,
                                                           Hb, (__half2*)Zr16, N, H3);
    spmm_h1<<<h1Blocks, 256>>>((const uint2*)Zr16, (float4*)Hb, (uint2*)Zs16,
                               ptr, srcIdx, enorm, dis, sc + H3 + 60, sh + H3 + 60, N);
    spmm_h2<<<h2Blocks, 256>>>((const uint2*)Zs16, (float4*)Hb,
                               ptr, srcIdx, enorm, dis, sc + H3 + 120, sh + H3 + 120, N);

    // ---- layer 3 (K=180) ----
    gemm_conv_fused<<<gemmBlocks, 512, FUSED_SMEM_BYTES>>>(Hb, conv3_W,
                                                           sc + 2 * H3, sh + 2 * H3,
                                                           Ha, (__half2*)Zr16, N, H3);
    spmm_h1<<<h1Blocks, 256>>>((const uint2*)Zr16, (float4*)Ha, (uint2*)Zs16,
                               ptr, srcIdx, enorm, dis, sc + 2 * H3 + 60, sh + 2 * H3 + 60, N);
    spmm_h2<<<h2Blocks, 256>>>((const uint2*)Zs16, (float4*)Ha,
                               ptr, srcIdx, enorm, dis, sc + 2 * H3 + 120, sh + 2 * H3 + 120, N);

    // ---- final linear ----
    gemm_final<<<gemmBlocks, 256, GEMM_SMEM_BYTES>>>(Ha, lin_W, lin_b, out, N, H3, CC);
}